// round 14
// baseline (speedup 1.0000x reference)
#include <cuda_runtime.h>
#include <cuda_fp16.h>
#include <cstdint>
#include <math.h>

// ---------------- problem constants ----------------
#define BB 8
#define TT 64
#define EE 128
#define CC 256
#define HH2 512          // conv hidden
#define MM 1024          // mlp hidden
#define RROWS 65536      // B*T*E
#define LNEPS 1e-5f

// ---------------- device scratch ----------------
__device__ __align__(128) __half g_xs16[RROWS * CC];    // xs fp16
__device__ __align__(128) __half g_qkvh[RROWS * 768];   // q|k|v fp16
__device__ __align__(128) __half g_o16 [RROWS * CC];    // attn out fp16
__device__ __align__(128) float  g_x1  [RROWS * CC];    // x1 fp32
__device__ __align__(128) __half g_xt16[RROWS * CC];    // LN(x1) fp16
__device__ __align__(128) __half g_y1h [RROWS * HH2];   // conv1 out fp16
__device__ __align__(128) float  g_x2  [RROWS * CC];    // x2 fp32
__device__ __align__(128) __half g_xm16[RROWS * CC];    // LN(x2) fp16
__device__ __align__(128) __half g_bigh[RROWS * MM];    // mlp hidden fp16
// fp16 weights, all [N][K] K-major
__device__ __align__(128) __half g_hqkv[768 * CC];
__device__ __align__(128) __half g_hp  [CC * CC];
__device__ __align__(128) __half g_hw1 [HH2 * 768];     // conv1: [h][kk], kk=j*256+c
__device__ __align__(128) __half g_hw2 [CC * HH2];
__device__ __align__(128) __half g_hf1 [MM * CC];
__device__ __align__(128) __half g_hf2 [CC * MM];
__device__ __align__(128) float g_maskf[EE * EE];       // 0.5 * adj_mask
__device__ __align__(128) float g_bn1s[HH2], g_bn1b[HH2], g_bn2s[CC], g_bn2b[CC];

// ---------------- helpers ----------------
__device__ __forceinline__ uint32_t smem_u32(const void* p)
{
    uint32_t a;
    asm("{ .reg .u64 t; cvta.to.shared.u64 t, %1; cvt.u32.u64 %0, t; }" : "=r"(a) : "l"(p));
    return a;
}
__device__ __forceinline__ void mma16(float* d, const uint4& a, const uint2& b)
{
    asm volatile("mma.sync.aligned.m16n8k16.row.col.f32.f16.f16.f32 "
                 "{%0,%1,%2,%3}, {%4,%5,%6,%7}, {%8,%9}, {%0,%1,%2,%3};"
                 : "+f"(d[0]), "+f"(d[1]), "+f"(d[2]), "+f"(d[3])
                 : "r"(a.x), "r"(a.y), "r"(a.z), "r"(a.w), "r"(b.x), "r"(b.y));
}
__device__ __forceinline__ uint4 ldsm4(uint32_t addr)
{
    uint4 r;
    asm volatile("ldmatrix.sync.aligned.m8n8.x4.shared.b16 {%0,%1,%2,%3}, [%4];"
                 : "=r"(r.x), "=r"(r.y), "=r"(r.z), "=r"(r.w) : "r"(addr));
    return r;
}
__device__ __forceinline__ void cpa16(uint32_t dst, const void* src)
{
    asm volatile("cp.async.cg.shared.global [%0], [%1], 16;" :: "r"(dst), "l"(src));
}
__device__ __forceinline__ void cpa16z(uint32_t dst, const void* src, int srcsize)
{
    asm volatile("cp.async.cg.shared.global [%0], [%1], 16, %2;"
                 :: "r"(dst), "l"(src), "r"(srcsize));
}
__device__ __forceinline__ void l2_prefetch(const void* p)
{
    asm volatile("prefetch.global.L2 [%0];" :: "l"(p));
}
#define CP_COMMIT() asm volatile("cp.async.commit_group;" ::: "memory")
#define CP_WAIT2()  asm volatile("cp.async.wait_group 2;" ::: "memory")

__device__ __forceinline__ float gelu_exact(float v)
{
    return 0.5f * v * (1.f + erff(v * 0.70710678118654752f));
}

// ---------------- merged prep + LN(x) ----------------
__device__ __forceinline__ void row_stats(float v, int tid, float& mean, float& rstd)
{
    __shared__ float sa[8], sb[8];
    __syncthreads();
    float s = v, s2 = v * v;
    #pragma unroll
    for (int o = 16; o; o >>= 1) {
        s  += __shfl_down_sync(0xffffffffu, s,  o);
        s2 += __shfl_down_sync(0xffffffffu, s2, o);
    }
    int lane = tid & 31, wid = tid >> 5;
    if (!lane) { sa[wid] = s; sb[wid] = s2; }
    __syncthreads();
    if (tid < 32) {
        s  = (tid < 8) ? sa[tid] : 0.f;
        s2 = (tid < 8) ? sb[tid] : 0.f;
        #pragma unroll
        for (int o = 4; o; o >>= 1) {
            s  += __shfl_down_sync(0xffffffffu, s,  o);
            s2 += __shfl_down_sync(0xffffffffu, s2, o);
        }
        if (!tid) {
            float m = s * (1.f / CC);
            sa[0] = m;
            sb[0] = rsqrtf(s2 * (1.f / CC) - m * m + LNEPS);
        }
    }
    __syncthreads();
    mean = sa[0]; rstd = sb[0];
}

__global__ void prep_ln_kernel(const float* __restrict__ x,
                               const float* __restrict__ n1w, const float* __restrict__ n1b,
                               __half* __restrict__ xs16,
                               const float* __restrict__ qw, const float* __restrict__ kw,
                               const float* __restrict__ vw, const float* __restrict__ pw,
                               const float* __restrict__ w1, const float* __restrict__ w2,
                               const float* __restrict__ f1, const float* __restrict__ f2,
                               const int* __restrict__ mask,
                               const float* __restrict__ b1w, const float* __restrict__ b1b,
                               const float* __restrict__ b1m, const float* __restrict__ b1v,
                               const float* __restrict__ b2w, const float* __restrict__ b2b,
                               const float* __restrict__ b2m, const float* __restrict__ b2v)
{
    int tid = threadIdx.x;
    int idx = blockIdx.x * 256 + tid;
    if (idx < 768 * CC) {
        int n = idx >> 8, k = idx & 255;
        const float* src = (n < 256) ? qw : (n < 512) ? kw : vw;
        g_hqkv[idx] = __float2half(src[k * CC + (n & 255)]);
    }
    if (idx < CC * CC) {
        int n = idx >> 8, k = idx & 255;
        g_hp[idx] = __float2half(pw[k * CC + n]);
    }
    if (idx < HH2 * 768) {
        int h = idx / 768, kk = idx % 768;
        int j = kk >> 8, c = kk & 255;
        g_hw1[idx] = __float2half(w1[h * 768 + c * 3 + j]);
    }
    if (idx < CC * HH2) g_hw2[idx] = __float2half(w2[idx]);
    if (idx < MM * CC) {
        int n = idx >> 8, k = idx & 255;
        g_hf1[idx] = __float2half(f1[k * MM + n]);
    }
    if (idx < CC * MM) {
        int n = idx >> 10, k = idx & 1023;
        g_hf2[idx] = __float2half(f2[k * CC + n]);
    }
    if (idx < EE * EE) g_maskf[idx] = 0.5f * (float)mask[idx];
    if (idx < HH2) {
        float s = b1w[idx] * rsqrtf(b1v[idx] + LNEPS);
        g_bn1s[idx] = s;
        g_bn1b[idx] = b1b[idx] - b1m[idx] * s;
    }
    if (idx < CC) {
        float s = b2w[idx] * rsqrtf(b2v[idx] + LNEPS);
        g_bn2s[idx] = s;
        g_bn2b[idx] = b2b[idx] - b2m[idx] * s;
    }
    size_t ridx = (size_t)blockIdx.x * CC + tid;
    float v = x[ridx];
    float mean, rstd;
    row_stats(v, tid, mean, rstd);
    xs16[ridx] = __float2half((v - mean) * rstd * n1w[tid] + n1b[tid]);
}

// ---------------- tensor-core attention (R12 verified): 2 bt per CTA -----------
#define MSTR 136
#define QSTR 40
#define VSTR 136
static constexpr int ATT_SMEM = 64000;

__global__ void __launch_bounds__(256, 2) attn_mma(const __half* __restrict__ QKV,
                                                   __half* __restrict__ O)
{
    extern __shared__ __align__(128) __half sm[];
    __half* maskS = sm;
    __half* Qs = sm + 17408;
    __half* Ks = Qs + 5120;
    __half* Vt = Ks + 5120;
    const int tid = threadIdx.x, w = tid >> 5, lane = tid & 31;
    const int r = lane >> 2, c = lane & 3;
    const int eBase = w * 16;

    for (int i = tid; i < 128 * 32; i += 256) {
        int e = i >> 5, f4 = (i & 31) * 4;
        float4 mv = *(const float4*)&g_maskf[e * 128 + f4];
        __half2 h0 = __floats2half2_rn(mv.x, mv.y);
        __half2 h1 = __floats2half2_rn(mv.z, mv.w);
        *(uint2*)&maskS[e * MSTR + f4] = make_uint2(*(uint32_t*)&h0, *(uint32_t*)&h1);
    }
    __syncthreads();

    const int se = tid >> 1, sp = tid & 1;

    #pragma unroll 1
    for (int bt = blockIdx.x; bt < BB * TT; bt += 256) {
        const __half* qbase = QKV + (size_t)bt * 128 * 768;
        for (int h = 0; h < 8; h++) {
            {
                const __half* row = qbase + (size_t)se * 768 + h * 32 + sp * 16;
                uint4 q0 = *(const uint4*)(row);
                uint4 q1 = *(const uint4*)(row + 8);
                *(uint4*)&Qs[se * QSTR + sp * 16]     = q0;
                *(uint4*)&Qs[se * QSTR + sp * 16 + 8] = q1;
                uint4 k0 = *(const uint4*)(row + 256);
                uint4 k1 = *(const uint4*)(row + 264);
                *(uint4*)&Ks[se * QSTR + sp * 16]     = k0;
                *(uint4*)&Ks[se * QSTR + sp * 16 + 8] = k1;
                uint4 v0 = *(const uint4*)(row + 512);
                uint4 v1 = *(const uint4*)(row + 520);
                const __half* vh0 = (const __half*)&v0;
                const __half* vh1 = (const __half*)&v1;
                #pragma unroll
                for (int i = 0; i < 8; i++) {
                    Vt[(sp * 16 + i) * VSTR + se]     = vh0[i];
                    Vt[(sp * 16 + 8 + i) * VSTR + se] = vh1[i];
                }
            }
            __syncthreads();

            uint4 aQ[2];
            #pragma unroll
            for (int ks = 0; ks < 2; ks++) {
                const __half* q0 = &Qs[(eBase + r) * QSTR + ks * 16 + 2 * c];
                aQ[ks].x = *(const uint32_t*)q0;
                aQ[ks].y = *(const uint32_t*)(q0 + 8 * QSTR);
                aQ[ks].z = *(const uint32_t*)(q0 + 8);
                aQ[ks].w = *(const uint32_t*)(q0 + 8 * QSTR + 8);
            }

            float oacc[4][4] = {};
            #pragma unroll
            for (int ph = 0; ph < 2; ph++) {
                float sacc[8][4] = {};
                #pragma unroll
                for (int nt = 0; nt < 8; nt++) {
                    const __half* kp = &Ks[(ph * 64 + nt * 8 + r) * QSTR + 2 * c];
                    #pragma unroll
                    for (int ks = 0; ks < 2; ks++) {
                        uint2 bf;
                        bf.x = *(const uint32_t*)(kp + ks * 16);
                        bf.y = *(const uint32_t*)(kp + ks * 16 + 8);
                        mma16(sacc[nt], aQ[ks], bf);
                    }
                }
                uint32_t wh[8][2];
                #pragma unroll
                for (int nt = 0; nt < 8; nt++) {
                    int fb = ph * 64 + nt * 8 + 2 * c;
                    float2 m0 = __half22float2(*(__half2*)&maskS[(eBase + r) * MSTR + fb]);
                    float2 m1 = __half22float2(*(__half2*)&maskS[(eBase + r + 8) * MSTR + fb]);
                    __half2 w0 = __floats2half2_rn(sacc[nt][0] * m0.x + 0.5f,
                                                   sacc[nt][1] * m0.y + 0.5f);
                    __half2 w1 = __floats2half2_rn(sacc[nt][2] * m1.x + 0.5f,
                                                   sacc[nt][3] * m1.y + 0.5f);
                    wh[nt][0] = *(uint32_t*)&w0;
                    wh[nt][1] = *(uint32_t*)&w1;
                }
                #pragma unroll
                for (int kk = 0; kk < 4; kk++) {
                    uint4 aw = make_uint4(wh[2 * kk][0], wh[2 * kk][1],
                                          wh[2 * kk + 1][0], wh[2 * kk + 1][1]);
                    #pragma unroll
                    for (int dt = 0; dt < 4; dt++) {
                        const __half* vp = &Vt[(dt * 8 + r) * VSTR + ph * 64 + kk * 16 + 2 * c];
                        uint2 bf;
                        bf.x = *(const uint32_t*)vp;
                        bf.y = *(const uint32_t*)(vp + 8);
                        mma16(oacc[dt], aw, bf);
                    }
                }
            }
            size_t ob = ((size_t)bt * 128 + eBase + r) * 256 + h * 32;
            #pragma unroll
            for (int dt = 0; dt < 4; dt++) {
                __half2 o0 = __floats2half2_rn(oacc[dt][0], oacc[dt][1]);
                __half2 o1 = __floats2half2_rn(oacc[dt][2], oacc[dt][3]);
                *(uint32_t*)&O[ob + dt * 8 + 2 * c]           = *(uint32_t*)&o0;
                *(uint32_t*)&O[ob + 8 * 256 + dt * 8 + 2 * c] = *(uint32_t*)&o1;
            }
            __syncthreads();
        }
    }
}

// ---------------- fp16 GEMM (verified) + L2 prefetch for residual epilogue -----
static constexpr int HG_SMEM = 65536;

template<int KDIM, bool GATHER, bool OUTH>
__global__ void __launch_bounds__(256, 2) h_gemm(
        const __half* __restrict__ A, const __half* __restrict__ Bt,
        void* __restrict__ Cv, int N,
        const float* __restrict__ colScale, const float* __restrict__ colShift,
        int doGelu, const float* __restrict__ res, float resCoef,
        const float* __restrict__ vMul)
{
    extern __shared__ __align__(128) char smem[];
    constexpr int NT = KDIM / 32;
    const int tid = threadIdx.x;
    const int w = tid >> 5, lane = tid & 31;
    const int n0 = blockIdx.x * 128, m0 = blockIdx.y * 128;
    const int mg = w >> 2, ng = w & 3;
    const uint32_t sbase = smem_u32(smem);

    float acc[4][4][4] = {};

    auto produce = [&](int stg, int kt) {
        uint32_t sb = sbase + stg * 16384;
        #pragma unroll
        for (int it = 0; it < 2; it++) {
            int id = tid + it * 256;
            int row = id >> 2, c = id & 3;
            uint32_t swoff = (uint32_t)((c ^ ((row >> 1) & 3)) * 16);
            uint32_t dstA = sb + row * 64 + swoff;
            if (GATHER) {
                int kg = kt * 32 + c * 8;
                int j = kg >> 8, cc = kg & 255;
                int t = ((m0 + row) >> 7) & 63;
                int tt = t + j - 1;
                bool valid = (unsigned)tt < 64u;
                const __half* src = A + ((size_t)(m0 + row) + (ptrdiff_t)(j - 1) * EE) * CC + cc;
                cpa16z(dstA, valid ? src : (const __half*)A, valid ? 16 : 0);
            } else {
                cpa16(dstA, A + (size_t)(m0 + row) * KDIM + kt * 32 + c * 8);
            }
            cpa16(sb + 8192 + row * 64 + swoff,
                  Bt + (size_t)(n0 + row) * KDIM + kt * 32 + c * 8);
        }
    };
    auto compute = [&](int stg) {
        uint32_t sb = sbase + stg * 16384;
        uint4 af[2][4];
        uint2 bf[2][4];
        #pragma unroll
        for (int ks = 0; ks < 2; ks++)
            #pragma unroll
            for (int mi = 0; mi < 4; mi++) {
                int row = mg * 64 + mi * 16 + (lane & 15);
                int ch = (ks * 2 + (lane >> 4)) ^ ((row >> 1) & 3);
                af[ks][mi] = ldsm4(sb + row * 64 + ch * 16);
            }
        #pragma unroll
        for (int ks = 0; ks < 2; ks++)
            #pragma unroll
            for (int p = 0; p < 2; p++) {
                int ni = 2 * p + (lane >> 4);
                int row = ng * 32 + ni * 8 + (lane & 7);
                int ch = (ks * 2 + ((lane >> 3) & 1)) ^ ((row >> 1) & 3);
                uint4 t4 = ldsm4(sb + 8192 + row * 64 + ch * 16);
                bf[ks][2 * p]     = make_uint2(t4.x, t4.y);
                bf[ks][2 * p + 1] = make_uint2(t4.z, t4.w);
            }
        #pragma unroll
        for (int ks = 0; ks < 2; ks++)
            #pragma unroll
            for (int mi = 0; mi < 4; mi++)
                #pragma unroll
                for (int ni = 0; ni < 4; ni++)
                    mma16(acc[mi][ni], af[ks][mi], bf[ks][ni]);
    };

    #pragma unroll
    for (int s = 0; s < 3; s++) {
        if (s < NT) produce(s, s);
        CP_COMMIT();
    }
    #pragma unroll 1
    for (int kt = 0; kt < NT; kt++) {
        CP_WAIT2();
        __syncthreads();
        if (kt + 3 < NT) produce((kt + 3) & 3, kt + 3);
        CP_COMMIT();
        // warm L2 for the residual epilogue while the load pipe is idle
        if (res && kt == NT - 3) {
            #pragma unroll
            for (int it = 0; it < 2; it++) {
                int id = tid + it * 256;       // 512 lines: 128 rows x 4 x 128B
                int row = id >> 2, seg = id & 3;
                l2_prefetch((const char*)(res + (size_t)(m0 + row) * N + n0) + seg * 128);
            }
        }
        compute(kt & 3);
    }

    const float vm = vMul ? *vMul : 1.0f;
    #pragma unroll
    for (int mi = 0; mi < 4; mi++) {
        #pragma unroll
        for (int ni = 0; ni < 4; ni++) {
            int r0 = m0 + (mg * 4 + mi) * 16 + (lane >> 2);
            int c0 = n0 + (ng * 4 + ni) * 8 + 2 * (lane & 3);
            #pragma unroll
            for (int half = 0; half < 2; half++) {
                int row = r0 + half * 8;
                float v0 = acc[mi][ni][half * 2 + 0];
                float v1 = acc[mi][ni][half * 2 + 1];
                size_t base = (size_t)row * N + c0;
                if (colScale) {
                    v0 = v0 * colScale[c0] + colShift[c0];
                    v1 = v1 * colScale[c0 + 1] + colShift[c0 + 1];
                } else if (colShift) {
                    v0 += colShift[c0];
                    v1 += colShift[c0 + 1];
                }
                if (doGelu) { v0 = gelu_exact(v0); v1 = gelu_exact(v1); }
                if (res) {
                    float2 r2 = *(const float2*)(res + base);
                    v0 = resCoef * r2.x + vm * v0;
                    v1 = resCoef * r2.y + vm * v1;
                }
                if (OUTH) {
                    __half2 h2v = __floats2half2_rn(v0, v1);
                    *(__half2*)((__half*)Cv + base) = h2v;
                } else {
                    *(float2*)((float*)Cv + base) = make_float2(v0, v1);
                }
            }
        }
    }
}

// ---------------- GEMM + fused row-LN epilogue + L2 prefetch -------------------
static constexpr int HGL_SMEM = 4 * 20480 + 4096 + 512;

template<int KDIM, bool DUAL>
__global__ void __launch_bounds__(256, 2) h_gemm_lnrow(
        const __half* __restrict__ A, const __half* __restrict__ Bt,
        const float* __restrict__ colScale, const float* __restrict__ colShift,
        const float* __restrict__ resid1, const __half* __restrict__ resid2h,
        const float* __restrict__ gamma,
        const float* __restrict__ lnw1, const float* __restrict__ lnb1,
        const float* __restrict__ lnw2, const float* __restrict__ lnb2,
        float* __restrict__ out32, __half* __restrict__ out16)
{
    extern __shared__ __align__(128) char smem[];
    constexpr int NT = KDIM / 32;
    const int tid = threadIdx.x;
    const int wp = tid >> 5, lane = tid & 31;
    const int m0 = blockIdx.y * 64;
    const int ng = wp;
    const uint32_t sbase = smem_u32(smem);
    float* ps    = (float*)(smem + 81920);
    float* pq    = ps + 512;
    float* mstat = pq + 512;
    float* rstat = mstat + 64;

    float acc[4][4][4] = {};

    auto produce = [&](int stg, int kt) {
        uint32_t sb = sbase + stg * 20480;
        {
            int row = tid >> 2, c = tid & 3;
            uint32_t swoff = (uint32_t)((c ^ ((row >> 1) & 3)) * 16);
            cpa16(sb + row * 64 + swoff, A + (size_t)(m0 + row) * KDIM + kt * 32 + c * 8);
        }
        #pragma unroll
        for (int it = 0; it < 4; it++) {
            int id = tid + it * 256;
            int row = id >> 2, c = id & 3;
            uint32_t swoff = (uint32_t)((c ^ ((row >> 1) & 3)) * 16);
            cpa16(sb + 4096 + row * 64 + swoff, Bt + (size_t)row * KDIM + kt * 32 + c * 8);
        }
    };
    auto compute = [&](int stg) {
        uint32_t sb = sbase + stg * 20480;
        uint4 af[2][4];
        uint2 bf[2][4];
        #pragma unroll
        for (int ks = 0; ks < 2; ks++)
            #pragma unroll
            for (int mi = 0; mi < 4; mi++) {
                int row = mi * 16 + (lane & 15);
                int ch = (ks * 2 + (lane >> 4)) ^ ((row >> 1) & 3);
                af[ks][mi] = ldsm4(sb + row * 64 + ch * 16);
            }
        #pragma unroll
        for (int ks = 0; ks < 2; ks++)
            #pragma unroll
            for (int p = 0; p < 2; p++) {
                int ni = 2 * p + (lane >> 4);
                int row = ng * 32 + ni * 8 + (lane & 7);
                int ch = (ks * 2 + ((lane >> 3) & 1)) ^ ((row >> 1) & 3);
                uint4 t4 = ldsm4(sb + 4096 + row * 64 + ch * 16);
                bf[ks][2 * p]     = make_uint2(t4.x, t4.y);
                bf[ks][2 * p + 1] = make_uint2(t4.z, t4.w);
            }
        #pragma unroll
        for (int ks = 0; ks < 2; ks++)
            #pragma unroll
            for (int mi = 0; mi < 4; mi++)
                #pragma unroll
                for (int ni = 0; ni < 4; ni++)
                    mma16(acc[mi][ni], af[ks][mi], bf[ks][ni]);
    };

    #pragma unroll
    for (int s = 0; s < 3; s++) {
        if (s < NT) produce(s, s);
        CP_COMMIT();
    }
    #pragma unroll 1
    for (int kt = 0; kt < NT; kt++) {
        CP_WAIT2();
        __syncthreads();
        if (kt + 3 < NT) produce((kt + 3) & 3, kt + 3);
        CP_COMMIT();
        // warm L2 for epilogue residual reads (resid1: 64 rows x 1KB = 512 lines;
        // resid2h: 64 rows x 512B = 256 lines)
        if (kt == NT - 3) {
            #pragma unroll
            for (int it = 0; it < 2; it++) {
                int id = tid + it * 256;
                int row = id >> 3, seg = id & 7;
                l2_prefetch((const char*)(resid1 + (size_t)(m0 + row) * 256) + seg * 128);
            }
            if (DUAL) {
                int row = tid >> 2, seg = tid & 3;
                l2_prefetch((const char*)(resid2h + (size_t)(m0 + row) * 256) + seg * 128);
            }
        }
        compute(kt & 3);
    }

    auto rowreduce = [&]() {
        #pragma unroll
        for (int mi = 0; mi < 4; mi++) {
            #pragma unroll
            for (int half = 0; half < 2; half++) {
                float s = 0.f, q2 = 0.f;
                #pragma unroll
                for (int ni = 0; ni < 4; ni++) {
                    float a0 = acc[mi][ni][half * 2 + 0];
                    float a1 = acc[mi][ni][half * 2 + 1];
                    s  += a0 + a1;
                    q2 += a0 * a0 + a1 * a1;
                }
                #pragma unroll
                for (int o = 1; o <= 2; o <<= 1) {
                    s  += __shfl_xor_sync(0xffffffffu, s,  o);
                    q2 += __shfl_xor_sync(0xffffffffu, q2, o);
                }
                if ((lane & 3) == 0) {
                    int r = mi * 16 + 8 * half + (lane >> 2);
                    ps[wp * 64 + r] = s;
                    pq[wp * 64 + r] = q2;
                }
            }
        }
        __syncthreads();
        if (tid < 64) {
            float S = 0.f, Q = 0.f;
            #pragma unroll
            for (int w8 = 0; w8 < 8; w8++) { S += ps[w8 * 64 + tid]; Q += pq[w8 * 64 + tid]; }
            float m = S * (1.f / 256.f);
            mstat[tid] = m;
            rstat[tid] = rsqrtf(Q * (1.f / 256.f) - m * m + LNEPS);
        }
        __syncthreads();
    };

    const float g = gamma[0];

    #pragma unroll
    for (int mi = 0; mi < 4; mi++)
        #pragma unroll
        for (int ni = 0; ni < 4; ni++)
            #pragma unroll
            for (int half = 0; half < 2; half++) {
                int c0 = ng * 32 + ni * 8 + 2 * (lane & 3);
                if (DUAL) {
                    acc[mi][ni][half * 2 + 0] += colShift[c0];
                    acc[mi][ni][half * 2 + 1] += colShift[c0 + 1];
                } else {
                    acc[mi][ni][half * 2 + 0] = acc[mi][ni][half * 2 + 0] * colScale[c0] + colShift[c0];
                    acc[mi][ni][half * 2 + 1] = acc[mi][ni][half * 2 + 1] * colScale[c0 + 1] + colShift[c0 + 1];
                }
            }

    if (DUAL) {
        rowreduce();
        #pragma unroll
        for (int mi = 0; mi < 4; mi++)
            #pragma unroll
            for (int ni = 0; ni < 4; ni++)
                #pragma unroll
                for (int half = 0; half < 2; half++) {
                    int rl = mi * 16 + (lane >> 2) + 8 * half;
                    int c0 = ng * 32 + ni * 8 + 2 * (lane & 3);
                    size_t base = (size_t)(m0 + rl) * 256 + c0;
                    float m = mstat[rl], ir = rstat[rl];
                    float2 w1v = *(const float2*)(lnw1 + c0);
                    float2 b1v = *(const float2*)(lnb1 + c0);
                    float v0 = acc[mi][ni][half * 2 + 0];
                    float v1 = acc[mi][ni][half * 2 + 1];
                    float l0 = (v0 - m) * ir * w1v.x + b1v.x;
                    float l1 = (v1 - m) * ir * w1v.y + b1v.y;
                    float2 xr = *(const float2*)(resid1 + base);
                    float2 xsf = __half22float2(*(const __half2*)(resid2h + base));
                    float xv0 = xr.x + xsf.x + g * l0;
                    float xv1 = xr.y + xsf.y + g * l1;
                    *(float2*)(out32 + base) = make_float2(xv0, xv1);
                    acc[mi][ni][half * 2 + 0] = xv0;
                    acc[mi][ni][half * 2 + 1] = xv1;
                }
        rowreduce();
        #pragma unroll
        for (int mi = 0; mi < 4; mi++)
            #pragma unroll
            for (int ni = 0; ni < 4; ni++)
                #pragma unroll
                for (int half = 0; half < 2; half++) {
                    int rl = mi * 16 + (lane >> 2) + 8 * half;
                    int c0 = ng * 32 + ni * 8 + 2 * (lane & 3);
                    size_t base = (size_t)(m0 + rl) * 256 + c0;
                    float m = mstat[rl], ir = rstat[rl];
                    float2 w2v = *(const float2*)(lnw2 + c0);
                    float2 b2v = *(const float2*)(lnb2 + c0);
                    float t0 = (acc[mi][ni][half * 2 + 0] - m) * ir * w2v.x + b2v.x;
                    float t1 = (acc[mi][ni][half * 2 + 1] - m) * ir * w2v.y + b2v.y;
                    *(__half2*)(out16 + base) = __floats2half2_rn(t0, t1);
                }
    } else {
        #pragma unroll
        for (int mi = 0; mi < 4; mi++)
            #pragma unroll
            for (int ni = 0; ni < 4; ni++)
                #pragma unroll
                for (int half = 0; half < 2; half++) {
                    int rl = mi * 16 + (lane >> 2) + 8 * half;
                    int c0 = ng * 32 + ni * 8 + 2 * (lane & 3);
                    size_t base = (size_t)(m0 + rl) * 256 + c0;
                    float2 xr = *(const float2*)(resid1 + base);
                    float xv0 = 2.f * xr.x + g * acc[mi][ni][half * 2 + 0];
                    float xv1 = 2.f * xr.y + g * acc[mi][ni][half * 2 + 1];
                    *(float2*)(out32 + base) = make_float2(xv0, xv1);
                    acc[mi][ni][half * 2 + 0] = xv0;
                    acc[mi][ni][half * 2 + 1] = xv1;
                }
        rowreduce();
        #pragma unroll
        for (int mi = 0; mi < 4; mi++)
            #pragma unroll
            for (int ni = 0; ni < 4; ni++)
                #pragma unroll
                for (int half = 0; half < 2; half++) {
                    int rl = mi * 16 + (lane >> 2) + 8 * half;
                    int c0 = ng * 32 + ni * 8 + 2 * (lane & 3);
                    size_t base = (size_t)(m0 + rl) * 256 + c0;
                    float m = mstat[rl], ir = rstat[rl];
                    float2 w1v = *(const float2*)(lnw1 + c0);
                    float2 b1v = *(const float2*)(lnb1 + c0);
                    float t0 = (acc[mi][ni][half * 2 + 0] - m) * ir * w1v.x + b1v.x;
                    float t1 = (acc[mi][ni][half * 2 + 1] - m) * ir * w1v.y + b1v.y;
                    *(__half2*)(out16 + base) = __floats2half2_rn(t0, t1);
                }
    }
}

// -------------------------------- launcher --------------------------------
template<typename T>
static T* symaddr(const void* sym)
{
    void* p = nullptr;
    cudaGetSymbolAddress(&p, sym);
    return (T*)p;
}

extern "C" void kernel_launch(void* const* d_in, const int* in_sizes, int n_in,
                              void* d_out, int out_size)
{
    const float* x       = (const float*)d_in[0];
    const int*   adj     = (const int*)  d_in[1];
    const float* n1_w    = (const float*)d_in[2];
    const float* n1_b    = (const float*)d_in[3];
    const float* q_w     = (const float*)d_in[4];
    const float* k_w     = (const float*)d_in[5];
    const float* v_w     = (const float*)d_in[6];
    const float* proj_w  = (const float*)d_in[7];
    const float* proj_b  = (const float*)d_in[8];
    const float* on_w    = (const float*)d_in[9];
    const float* on_b    = (const float*)d_in[10];
    const float* gamma_s = (const float*)d_in[11];
    const float* conv1_w = (const float*)d_in[12];
    const float* bn1_w   = (const float*)d_in[13];
    const float* bn1_b   = (const float*)d_in[14];
    const float* bn1_m   = (const float*)d_in[15];
    const float* bn1_v   = (const float*)d_in[16];
    const float* conv2_w = (const float*)d_in[17];
    const float* bn2_w   = (const float*)d_in[18];
    const float* bn2_b   = (const float*)d_in[19];
    const float* bn2_m   = (const float*)d_in[20];
    const float* bn2_v   = (const float*)d_in[21];
    const float* tn_w    = (const float*)d_in[22];
    const float* tn_b    = (const float*)d_in[23];
    const float* gamma_t = (const float*)d_in[24];
    const float* n3_w    = (const float*)d_in[25];
    const float* n3_b    = (const float*)d_in[26];
    const float* fc1_w   = (const float*)d_in[27];
    const float* fc1_b   = (const float*)d_in[28];
    const float* fc2_w   = (const float*)d_in[29];
    const float* fc2_b   = (const float*)d_in[30];
    float* out = (float*)d_out;

    __half* xs16 = symaddr<__half>(g_xs16);
    __half* qkvh = symaddr<__half>(g_qkvh);
    __half* o16  = symaddr<__half>(g_o16);
    float*  x1   = symaddr<float >(g_x1);
    __half* xt16 = symaddr<__half>(g_xt16);
    __half* y1h  = symaddr<__half>(g_y1h);
    float*  x2   = symaddr<float >(g_x2);
    __half* xm16 = symaddr<__half>(g_xm16);
    __half* bigh = symaddr<__half>(g_bigh);
    __half* hqkv = symaddr<__half>(g_hqkv);
    __half* hp   = symaddr<__half>(g_hp);
    __half* hw1  = symaddr<__half>(g_hw1);
    __half* hw2  = symaddr<__half>(g_hw2);
    __half* hf1  = symaddr<__half>(g_hf1);
    __half* hf2  = symaddr<__half>(g_hf2);
    float* bn1s = symaddr<float>(g_bn1s);
    float* bn1b = symaddr<float>(g_bn1b);
    float* bn2s = symaddr<float>(g_bn2s);
    float* bn2b = symaddr<float>(g_bn2b);

    cudaFuncSetAttribute(h_gemm<256,  false, true >, cudaFuncAttributeMaxDynamicSharedMemorySize, HG_SMEM);
    cudaFuncSetAttribute(h_gemm<768,  true,  true >, cudaFuncAttributeMaxDynamicSharedMemorySize, HG_SMEM);
    cudaFuncSetAttribute(h_gemm<1024, false, false>, cudaFuncAttributeMaxDynamicSharedMemorySize, HG_SMEM);
    cudaFuncSetAttribute(h_gemm_lnrow<256, true >, cudaFuncAttributeMaxDynamicSharedMemorySize, HGL_SMEM);
    cudaFuncSetAttribute(h_gemm_lnrow<512, false>, cudaFuncAttributeMaxDynamicSharedMemorySize, HGL_SMEM);
    cudaFuncSetAttribute(attn_mma, cudaFuncAttributeMaxDynamicSharedMemorySize, ATT_SMEM);

    // 0) merged prep + LN(x) -> xs16
    prep_ln_kernel<<<RROWS, 256>>>(x, n1_w, n1_b, xs16,
                                   q_w, k_w, v_w, proj_w, conv1_w, conv2_w, fc1_w, fc2_w,
                                   adj, bn1_w, bn1_b, bn1_m, bn1_v,
                                   bn2_w, bn2_b, bn2_m, bn2_v);

    // 1) fused QKV GEMM -> [R][768] fp16
    h_gemm<256, false, true><<<dim3(6, 512), 256, HG_SMEM>>>(xs16, hqkv, qkvh, 768,
        nullptr, nullptr, 0, nullptr, 0.f, nullptr);

    // 2) tensor-core masked attention (single wave: 256 CTAs x 2 bt)
    attn_mma<<<256, 256, ATT_SMEM>>>(qkvh, o16);

    // 3) proj GEMM + bias + LN + residual + LN -> x1 (fp32), xt16 (fp16)
    h_gemm_lnrow<256, true><<<dim3(1, 1024), 256, HGL_SMEM>>>(
        o16, hp, nullptr, proj_b, x, xs16, gamma_s,
        on_w, on_b, tn_w, tn_b, x1, xt16);

    // 4) conv1 (gathered) + BN1 + GELU -> y1 fp16
    h_gemm<768, true, true><<<dim3(4, 512), 256, HG_SMEM>>>(xt16, hw1, y1h, HH2,
        bn1s, bn1b, 1, nullptr, 0.f, nullptr);

    // 5) conv2 GEMM + BN2 + (x2 = 2*x1 + gamma_t*y) + LN -> x2, xm16
    h_gemm_lnrow<512, false><<<dim3(1, 1024), 256, HGL_SMEM>>>(
        y1h, hw2, bn2s, bn2b, x1, nullptr, gamma_t,
        n3_w, n3_b, nullptr, nullptr, x2, xm16);

    // 6) fc1 + bias + GELU -> big fp16
    h_gemm<256, false, true><<<dim3(8, 512), 256, HG_SMEM>>>(xm16, hf1, bigh, MM,
        nullptr, fc1_b, 1, nullptr, 0.f, nullptr);

    // 7) fc2 + bias + residual x2 -> out fp32
    h_gemm<1024, false, false><<<dim3(2, 512), 256, HG_SMEM>>>(bigh, hf2, out, CC,
        nullptr, fc2_b, 0, x2, 1.0f, nullptr);
}

// round 15
// speedup vs baseline: 1.0425x; 1.0425x over previous
#include <cuda_runtime.h>
#include <cuda_fp16.h>
#include <cstdint>
#include <math.h>

// ---------------- problem constants ----------------
#define BB 8
#define TT 64
#define EE 128
#define CC 256
#define HH2 512          // conv hidden
#define MM 1024          // mlp hidden
#define RROWS 65536      // B*T*E
#define LNEPS 1e-5f

// ---------------- device scratch ----------------
__device__ __align__(128) __half g_xs16[RROWS * CC];    // xs fp16
__device__ __align__(128) __half g_qkvh[RROWS * 768];   // q|k|v fp16
__device__ __align__(128) __half g_o16 [RROWS * CC];    // attn out fp16
__device__ __align__(128) __half g_x1h [RROWS * CC];    // x1 fp16
__device__ __align__(128) __half g_xt16[RROWS * CC];    // LN(x1) fp16
__device__ __align__(128) __half g_y1h [RROWS * HH2];   // conv1 out fp16
__device__ __align__(128) __half g_x2h [RROWS * CC];    // x2 fp16
__device__ __align__(128) __half g_xm16[RROWS * CC];    // LN(x2) fp16
__device__ __align__(128) __half g_bigh[RROWS * MM];    // mlp hidden fp16
// fp16 weights, all [N][K] K-major
__device__ __align__(128) __half g_hqkv[768 * CC];
__device__ __align__(128) __half g_hp  [CC * CC];
__device__ __align__(128) __half g_hw1 [HH2 * 768];     // conv1: [h][kk], kk=j*256+c
__device__ __align__(128) __half g_hw2 [CC * HH2];
__device__ __align__(128) __half g_hf1 [MM * CC];
__device__ __align__(128) __half g_hf2 [CC * MM];
__device__ __align__(128) float g_maskf[EE * EE];       // 0.5 * adj_mask
__device__ __align__(128) float g_bn1s[HH2], g_bn1b[HH2], g_bn2s[CC], g_bn2b[CC];

// ---------------- helpers ----------------
__device__ __forceinline__ uint32_t smem_u32(const void* p)
{
    uint32_t a;
    asm("{ .reg .u64 t; cvta.to.shared.u64 t, %1; cvt.u32.u64 %0, t; }" : "=r"(a) : "l"(p));
    return a;
}
__device__ __forceinline__ void mma16(float* d, const uint4& a, const uint2& b)
{
    asm volatile("mma.sync.aligned.m16n8k16.row.col.f32.f16.f16.f32 "
                 "{%0,%1,%2,%3}, {%4,%5,%6,%7}, {%8,%9}, {%0,%1,%2,%3};"
                 : "+f"(d[0]), "+f"(d[1]), "+f"(d[2]), "+f"(d[3])
                 : "r"(a.x), "r"(a.y), "r"(a.z), "r"(a.w), "r"(b.x), "r"(b.y));
}
__device__ __forceinline__ uint4 ldsm4(uint32_t addr)
{
    uint4 r;
    asm volatile("ldmatrix.sync.aligned.m8n8.x4.shared.b16 {%0,%1,%2,%3}, [%4];"
                 : "=r"(r.x), "=r"(r.y), "=r"(r.z), "=r"(r.w) : "r"(addr));
    return r;
}
__device__ __forceinline__ void cpa16(uint32_t dst, const void* src)
{
    asm volatile("cp.async.cg.shared.global [%0], [%1], 16;" :: "r"(dst), "l"(src));
}
__device__ __forceinline__ void cpa16z(uint32_t dst, const void* src, int srcsize)
{
    asm volatile("cp.async.cg.shared.global [%0], [%1], 16, %2;"
                 :: "r"(dst), "l"(src), "r"(srcsize));
}
#define CP_COMMIT() asm volatile("cp.async.commit_group;" ::: "memory")
#define CP_WAIT2()  asm volatile("cp.async.wait_group 2;" ::: "memory")

__device__ __forceinline__ float gelu_exact(float v)
{
    return 0.5f * v * (1.f + erff(v * 0.70710678118654752f));
}

// ---------------- merged prep + LN(x) ----------------
__device__ __forceinline__ void row_stats(float v, int tid, float& mean, float& rstd)
{
    __shared__ float sa[8], sb[8];
    __syncthreads();
    float s = v, s2 = v * v;
    #pragma unroll
    for (int o = 16; o; o >>= 1) {
        s  += __shfl_down_sync(0xffffffffu, s,  o);
        s2 += __shfl_down_sync(0xffffffffu, s2, o);
    }
    int lane = tid & 31, wid = tid >> 5;
    if (!lane) { sa[wid] = s; sb[wid] = s2; }
    __syncthreads();
    if (tid < 32) {
        s  = (tid < 8) ? sa[tid] : 0.f;
        s2 = (tid < 8) ? sb[tid] : 0.f;
        #pragma unroll
        for (int o = 4; o; o >>= 1) {
            s  += __shfl_down_sync(0xffffffffu, s,  o);
            s2 += __shfl_down_sync(0xffffffffu, s2, o);
        }
        if (!tid) {
            float m = s * (1.f / CC);
            sa[0] = m;
            sb[0] = rsqrtf(s2 * (1.f / CC) - m * m + LNEPS);
        }
    }
    __syncthreads();
    mean = sa[0]; rstd = sb[0];
}

__global__ void prep_ln_kernel(const float* __restrict__ x,
                               const float* __restrict__ n1w, const float* __restrict__ n1b,
                               __half* __restrict__ xs16,
                               const float* __restrict__ qw, const float* __restrict__ kw,
                               const float* __restrict__ vw, const float* __restrict__ pw,
                               const float* __restrict__ w1, const float* __restrict__ w2,
                               const float* __restrict__ f1, const float* __restrict__ f2,
                               const int* __restrict__ mask,
                               const float* __restrict__ b1w, const float* __restrict__ b1b,
                               const float* __restrict__ b1m, const float* __restrict__ b1v,
                               const float* __restrict__ b2w, const float* __restrict__ b2b,
                               const float* __restrict__ b2m, const float* __restrict__ b2v)
{
    int tid = threadIdx.x;
    int idx = blockIdx.x * 256 + tid;
    if (idx < 768 * CC) {
        int n = idx >> 8, k = idx & 255;
        const float* src = (n < 256) ? qw : (n < 512) ? kw : vw;
        g_hqkv[idx] = __float2half(src[k * CC + (n & 255)]);
    }
    if (idx < CC * CC) {
        int n = idx >> 8, k = idx & 255;
        g_hp[idx] = __float2half(pw[k * CC + n]);
    }
    if (idx < HH2 * 768) {
        int h = idx / 768, kk = idx % 768;
        int j = kk >> 8, c = kk & 255;
        g_hw1[idx] = __float2half(w1[h * 768 + c * 3 + j]);
    }
    if (idx < CC * HH2) g_hw2[idx] = __float2half(w2[idx]);
    if (idx < MM * CC) {
        int n = idx >> 8, k = idx & 255;
        g_hf1[idx] = __float2half(f1[k * MM + n]);
    }
    if (idx < CC * MM) {
        int n = idx >> 10, k = idx & 1023;
        g_hf2[idx] = __float2half(f2[k * CC + n]);
    }
    if (idx < EE * EE) g_maskf[idx] = 0.5f * (float)mask[idx];
    if (idx < HH2) {
        float s = b1w[idx] * rsqrtf(b1v[idx] + LNEPS);
        g_bn1s[idx] = s;
        g_bn1b[idx] = b1b[idx] - b1m[idx] * s;
    }
    if (idx < CC) {
        float s = b2w[idx] * rsqrtf(b2v[idx] + LNEPS);
        g_bn2s[idx] = s;
        g_bn2b[idx] = b2b[idx] - b2m[idx] * s;
    }
    size_t ridx = (size_t)blockIdx.x * CC + tid;
    float v = x[ridx];
    float mean, rstd;
    row_stats(v, tid, mean, rstd);
    xs16[ridx] = __float2half((v - mean) * rstd * n1w[tid] + n1b[tid]);
}

// ---------------- tensor-core attention (R12 verified): 2 bt per CTA -----------
#define MSTR 136
#define QSTR 40
#define VSTR 136
static constexpr int ATT_SMEM = 64000;

__global__ void __launch_bounds__(256, 2) attn_mma(const __half* __restrict__ QKV,
                                                   __half* __restrict__ O)
{
    extern __shared__ __align__(128) __half sm[];
    __half* maskS = sm;
    __half* Qs = sm + 17408;
    __half* Ks = Qs + 5120;
    __half* Vt = Ks + 5120;
    const int tid = threadIdx.x, w = tid >> 5, lane = tid & 31;
    const int r = lane >> 2, c = lane & 3;
    const int eBase = w * 16;

    for (int i = tid; i < 128 * 32; i += 256) {
        int e = i >> 5, f4 = (i & 31) * 4;
        float4 mv = *(const float4*)&g_maskf[e * 128 + f4];
        __half2 h0 = __floats2half2_rn(mv.x, mv.y);
        __half2 h1 = __floats2half2_rn(mv.z, mv.w);
        *(uint2*)&maskS[e * MSTR + f4] = make_uint2(*(uint32_t*)&h0, *(uint32_t*)&h1);
    }
    __syncthreads();

    const int se = tid >> 1, sp = tid & 1;

    #pragma unroll 1
    for (int bt = blockIdx.x; bt < BB * TT; bt += 256) {
        const __half* qbase = QKV + (size_t)bt * 128 * 768;
        for (int h = 0; h < 8; h++) {
            {
                const __half* row = qbase + (size_t)se * 768 + h * 32 + sp * 16;
                uint4 q0 = *(const uint4*)(row);
                uint4 q1 = *(const uint4*)(row + 8);
                *(uint4*)&Qs[se * QSTR + sp * 16]     = q0;
                *(uint4*)&Qs[se * QSTR + sp * 16 + 8] = q1;
                uint4 k0 = *(const uint4*)(row + 256);
                uint4 k1 = *(const uint4*)(row + 264);
                *(uint4*)&Ks[se * QSTR + sp * 16]     = k0;
                *(uint4*)&Ks[se * QSTR + sp * 16 + 8] = k1;
                uint4 v0 = *(const uint4*)(row + 512);
                uint4 v1 = *(const uint4*)(row + 520);
                const __half* vh0 = (const __half*)&v0;
                const __half* vh1 = (const __half*)&v1;
                #pragma unroll
                for (int i = 0; i < 8; i++) {
                    Vt[(sp * 16 + i) * VSTR + se]     = vh0[i];
                    Vt[(sp * 16 + 8 + i) * VSTR + se] = vh1[i];
                }
            }
            __syncthreads();

            uint4 aQ[2];
            #pragma unroll
            for (int ks = 0; ks < 2; ks++) {
                const __half* q0 = &Qs[(eBase + r) * QSTR + ks * 16 + 2 * c];
                aQ[ks].x = *(const uint32_t*)q0;
                aQ[ks].y = *(const uint32_t*)(q0 + 8 * QSTR);
                aQ[ks].z = *(const uint32_t*)(q0 + 8);
                aQ[ks].w = *(const uint32_t*)(q0 + 8 * QSTR + 8);
            }

            float oacc[4][4] = {};
            #pragma unroll
            for (int ph = 0; ph < 2; ph++) {
                float sacc[8][4] = {};
                #pragma unroll
                for (int nt = 0; nt < 8; nt++) {
                    const __half* kp = &Ks[(ph * 64 + nt * 8 + r) * QSTR + 2 * c];
                    #pragma unroll
                    for (int ks = 0; ks < 2; ks++) {
                        uint2 bf;
                        bf.x = *(const uint32_t*)(kp + ks * 16);
                        bf.y = *(const uint32_t*)(kp + ks * 16 + 8);
                        mma16(sacc[nt], aQ[ks], bf);
                    }
                }
                uint32_t wh[8][2];
                #pragma unroll
                for (int nt = 0; nt < 8; nt++) {
                    int fb = ph * 64 + nt * 8 + 2 * c;
                    float2 m0 = __half22float2(*(__half2*)&maskS[(eBase + r) * MSTR + fb]);
                    float2 m1 = __half22float2(*(__half2*)&maskS[(eBase + r + 8) * MSTR + fb]);
                    __half2 w0 = __floats2half2_rn(sacc[nt][0] * m0.x + 0.5f,
                                                   sacc[nt][1] * m0.y + 0.5f);
                    __half2 w1 = __floats2half2_rn(sacc[nt][2] * m1.x + 0.5f,
                                                   sacc[nt][3] * m1.y + 0.5f);
                    wh[nt][0] = *(uint32_t*)&w0;
                    wh[nt][1] = *(uint32_t*)&w1;
                }
                #pragma unroll
                for (int kk = 0; kk < 4; kk++) {
                    uint4 aw = make_uint4(wh[2 * kk][0], wh[2 * kk][1],
                                          wh[2 * kk + 1][0], wh[2 * kk + 1][1]);
                    #pragma unroll
                    for (int dt = 0; dt < 4; dt++) {
                        const __half* vp = &Vt[(dt * 8 + r) * VSTR + ph * 64 + kk * 16 + 2 * c];
                        uint2 bf;
                        bf.x = *(const uint32_t*)vp;
                        bf.y = *(const uint32_t*)(vp + 8);
                        mma16(oacc[dt], aw, bf);
                    }
                }
            }
            size_t ob = ((size_t)bt * 128 + eBase + r) * 256 + h * 32;
            #pragma unroll
            for (int dt = 0; dt < 4; dt++) {
                __half2 o0 = __floats2half2_rn(oacc[dt][0], oacc[dt][1]);
                __half2 o1 = __floats2half2_rn(oacc[dt][2], oacc[dt][3]);
                *(uint32_t*)&O[ob + dt * 8 + 2 * c]           = *(uint32_t*)&o0;
                *(uint32_t*)&O[ob + 8 * 256 + dt * 8 + 2 * c] = *(uint32_t*)&o1;
            }
            __syncthreads();
        }
    }
}

// ---------------- fp16 GEMM (verified); residual now fp16 ----------------------
static constexpr int HG_SMEM = 65536;

template<int KDIM, bool GATHER, bool OUTH>
__global__ void __launch_bounds__(256, 2) h_gemm(
        const __half* __restrict__ A, const __half* __restrict__ Bt,
        void* __restrict__ Cv, int N,
        const float* __restrict__ colScale, const float* __restrict__ colShift,
        int doGelu, const __half* __restrict__ res, float resCoef,
        const float* __restrict__ vMul)
{
    extern __shared__ __align__(128) char smem[];
    constexpr int NT = KDIM / 32;
    const int tid = threadIdx.x;
    const int w = tid >> 5, lane = tid & 31;
    const int n0 = blockIdx.x * 128, m0 = blockIdx.y * 128;
    const int mg = w >> 2, ng = w & 3;
    const uint32_t sbase = smem_u32(smem);

    float acc[4][4][4] = {};

    auto produce = [&](int stg, int kt) {
        uint32_t sb = sbase + stg * 16384;
        #pragma unroll
        for (int it = 0; it < 2; it++) {
            int id = tid + it * 256;
            int row = id >> 2, c = id & 3;
            uint32_t swoff = (uint32_t)((c ^ ((row >> 1) & 3)) * 16);
            uint32_t dstA = sb + row * 64 + swoff;
            if (GATHER) {
                int kg = kt * 32 + c * 8;
                int j = kg >> 8, cc = kg & 255;
                int t = ((m0 + row) >> 7) & 63;
                int tt = t + j - 1;
                bool valid = (unsigned)tt < 64u;
                const __half* src = A + ((size_t)(m0 + row) + (ptrdiff_t)(j - 1) * EE) * CC + cc;
                cpa16z(dstA, valid ? src : (const __half*)A, valid ? 16 : 0);
            } else {
                cpa16(dstA, A + (size_t)(m0 + row) * KDIM + kt * 32 + c * 8);
            }
            cpa16(sb + 8192 + row * 64 + swoff,
                  Bt + (size_t)(n0 + row) * KDIM + kt * 32 + c * 8);
        }
    };
    auto compute = [&](int stg) {
        uint32_t sb = sbase + stg * 16384;
        uint4 af[2][4];
        uint2 bf[2][4];
        #pragma unroll
        for (int ks = 0; ks < 2; ks++)
            #pragma unroll
            for (int mi = 0; mi < 4; mi++) {
                int row = mg * 64 + mi * 16 + (lane & 15);
                int ch = (ks * 2 + (lane >> 4)) ^ ((row >> 1) & 3);
                af[ks][mi] = ldsm4(sb + row * 64 + ch * 16);
            }
        #pragma unroll
        for (int ks = 0; ks < 2; ks++)
            #pragma unroll
            for (int p = 0; p < 2; p++) {
                int ni = 2 * p + (lane >> 4);
                int row = ng * 32 + ni * 8 + (lane & 7);
                int ch = (ks * 2 + ((lane >> 3) & 1)) ^ ((row >> 1) & 3);
                uint4 t4 = ldsm4(sb + 8192 + row * 64 + ch * 16);
                bf[ks][2 * p]     = make_uint2(t4.x, t4.y);
                bf[ks][2 * p + 1] = make_uint2(t4.z, t4.w);
            }
        #pragma unroll
        for (int ks = 0; ks < 2; ks++)
            #pragma unroll
            for (int mi = 0; mi < 4; mi++)
                #pragma unroll
                for (int ni = 0; ni < 4; ni++)
                    mma16(acc[mi][ni], af[ks][mi], bf[ks][ni]);
    };

    #pragma unroll
    for (int s = 0; s < 3; s++) {
        if (s < NT) produce(s, s);
        CP_COMMIT();
    }
    #pragma unroll 1
    for (int kt = 0; kt < NT; kt++) {
        CP_WAIT2();
        __syncthreads();
        if (kt + 3 < NT) produce((kt + 3) & 3, kt + 3);
        CP_COMMIT();
        compute(kt & 3);
    }

    const float vm = vMul ? *vMul : 1.0f;
    #pragma unroll
    for (int mi = 0; mi < 4; mi++) {
        #pragma unroll
        for (int ni = 0; ni < 4; ni++) {
            int r0 = m0 + (mg * 4 + mi) * 16 + (lane >> 2);
            int c0 = n0 + (ng * 4 + ni) * 8 + 2 * (lane & 3);
            #pragma unroll
            for (int half = 0; half < 2; half++) {
                int row = r0 + half * 8;
                float v0 = acc[mi][ni][half * 2 + 0];
                float v1 = acc[mi][ni][half * 2 + 1];
                size_t base = (size_t)row * N + c0;
                if (colScale) {
                    v0 = v0 * colScale[c0] + colShift[c0];
                    v1 = v1 * colScale[c0 + 1] + colShift[c0 + 1];
                } else if (colShift) {
                    v0 += colShift[c0];
                    v1 += colShift[c0 + 1];
                }
                if (doGelu) { v0 = gelu_exact(v0); v1 = gelu_exact(v1); }
                if (res) {
                    float2 r2 = __half22float2(*(const __half2*)(res + base));
                    v0 = resCoef * r2.x + vm * v0;
                    v1 = resCoef * r2.y + vm * v1;
                }
                if (OUTH) {
                    __half2 h2v = __floats2half2_rn(v0, v1);
                    *(__half2*)((__half*)Cv + base) = h2v;
                } else {
                    *(float2*)((float*)Cv + base) = make_float2(v0, v1);
                }
            }
        }
    }
}

// ---------------- GEMM + fused row-LN epilogue; outputs fp16 -------------------
// DUAL (proj):   v=acc+shift; LN(v)->ln; xv=resid1(f32 x)+resid2h(xs16)+g*ln;
//                outA=half(xv); LN(xv from fp32 acc)->out16
// single(conv2): v=acc*scale+shift; xv=2*resid2h(x1 fp16)+g*v; outA=half(xv);
//                LN(xv)->out16
static constexpr int HGL_SMEM = 4 * 20480 + 4096 + 512;

template<int KDIM, bool DUAL>
__global__ void __launch_bounds__(256, 2) h_gemm_lnrow(
        const __half* __restrict__ A, const __half* __restrict__ Bt,
        const float* __restrict__ colScale, const float* __restrict__ colShift,
        const float* __restrict__ resid1, const __half* __restrict__ resid2h,
        const float* __restrict__ gamma,
        const float* __restrict__ lnw1, const float* __restrict__ lnb1,
        const float* __restrict__ lnw2, const float* __restrict__ lnb2,
        __half* __restrict__ outA, __half* __restrict__ out16)
{
    extern __shared__ __align__(128) char smem[];
    constexpr int NT = KDIM / 32;
    const int tid = threadIdx.x;
    const int wp = tid >> 5, lane = tid & 31;
    const int m0 = blockIdx.y * 64;
    const int ng = wp;
    const uint32_t sbase = smem_u32(smem);
    float* ps    = (float*)(smem + 81920);
    float* pq    = ps + 512;
    float* mstat = pq + 512;
    float* rstat = mstat + 64;

    float acc[4][4][4] = {};

    auto produce = [&](int stg, int kt) {
        uint32_t sb = sbase + stg * 20480;
        {
            int row = tid >> 2, c = tid & 3;
            uint32_t swoff = (uint32_t)((c ^ ((row >> 1) & 3)) * 16);
            cpa16(sb + row * 64 + swoff, A + (size_t)(m0 + row) * KDIM + kt * 32 + c * 8);
        }
        #pragma unroll
        for (int it = 0; it < 4; it++) {
            int id = tid + it * 256;
            int row = id >> 2, c = id & 3;
            uint32_t swoff = (uint32_t)((c ^ ((row >> 1) & 3)) * 16);
            cpa16(sb + 4096 + row * 64 + swoff, Bt + (size_t)row * KDIM + kt * 32 + c * 8);
        }
    };
    auto compute = [&](int stg) {
        uint32_t sb = sbase + stg * 20480;
        uint4 af[2][4];
        uint2 bf[2][4];
        #pragma unroll
        for (int ks = 0; ks < 2; ks++)
            #pragma unroll
            for (int mi = 0; mi < 4; mi++) {
                int row = mi * 16 + (lane & 15);
                int ch = (ks * 2 + (lane >> 4)) ^ ((row >> 1) & 3);
                af[ks][mi] = ldsm4(sb + row * 64 + ch * 16);
            }
        #pragma unroll
        for (int ks = 0; ks < 2; ks++)
            #pragma unroll
            for (int p = 0; p < 2; p++) {
                int ni = 2 * p + (lane >> 4);
                int row = ng * 32 + ni * 8 + (lane & 7);
                int ch = (ks * 2 + ((lane >> 3) & 1)) ^ ((row >> 1) & 3);
                uint4 t4 = ldsm4(sb + 4096 + row * 64 + ch * 16);
                bf[ks][2 * p]     = make_uint2(t4.x, t4.y);
                bf[ks][2 * p + 1] = make_uint2(t4.z, t4.w);
            }
        #pragma unroll
        for (int ks = 0; ks < 2; ks++)
            #pragma unroll
            for (int mi = 0; mi < 4; mi++)
                #pragma unroll
                for (int ni = 0; ni < 4; ni++)
                    mma16(acc[mi][ni], af[ks][mi], bf[ks][ni]);
    };

    #pragma unroll
    for (int s = 0; s < 3; s++) {
        if (s < NT) produce(s, s);
        CP_COMMIT();
    }
    #pragma unroll 1
    for (int kt = 0; kt < NT; kt++) {
        CP_WAIT2();
        __syncthreads();
        if (kt + 3 < NT) produce((kt + 3) & 3, kt + 3);
        CP_COMMIT();
        compute(kt & 3);
    }

    auto rowreduce = [&]() {
        #pragma unroll
        for (int mi = 0; mi < 4; mi++) {
            #pragma unroll
            for (int half = 0; half < 2; half++) {
                float s = 0.f, q2 = 0.f;
                #pragma unroll
                for (int ni = 0; ni < 4; ni++) {
                    float a0 = acc[mi][ni][half * 2 + 0];
                    float a1 = acc[mi][ni][half * 2 + 1];
                    s  += a0 + a1;
                    q2 += a0 * a0 + a1 * a1;
                }
                #pragma unroll
                for (int o = 1; o <= 2; o <<= 1) {
                    s  += __shfl_xor_sync(0xffffffffu, s,  o);
                    q2 += __shfl_xor_sync(0xffffffffu, q2, o);
                }
                if ((lane & 3) == 0) {
                    int r = mi * 16 + 8 * half + (lane >> 2);
                    ps[wp * 64 + r] = s;
                    pq[wp * 64 + r] = q2;
                }
            }
        }
        __syncthreads();
        if (tid < 64) {
            float S = 0.f, Q = 0.f;
            #pragma unroll
            for (int w8 = 0; w8 < 8; w8++) { S += ps[w8 * 64 + tid]; Q += pq[w8 * 64 + tid]; }
            float m = S * (1.f / 256.f);
            mstat[tid] = m;
            rstat[tid] = rsqrtf(Q * (1.f / 256.f) - m * m + LNEPS);
        }
        __syncthreads();
    };

    const float g = gamma[0];

    #pragma unroll
    for (int mi = 0; mi < 4; mi++)
        #pragma unroll
        for (int ni = 0; ni < 4; ni++)
            #pragma unroll
            for (int half = 0; half < 2; half++) {
                int c0 = ng * 32 + ni * 8 + 2 * (lane & 3);
                if (DUAL) {
                    acc[mi][ni][half * 2 + 0] += colShift[c0];
                    acc[mi][ni][half * 2 + 1] += colShift[c0 + 1];
                } else {
                    acc[mi][ni][half * 2 + 0] = acc[mi][ni][half * 2 + 0] * colScale[c0] + colShift[c0];
                    acc[mi][ni][half * 2 + 1] = acc[mi][ni][half * 2 + 1] * colScale[c0 + 1] + colShift[c0 + 1];
                }
            }

    if (DUAL) {
        rowreduce();
        #pragma unroll
        for (int mi = 0; mi < 4; mi++)
            #pragma unroll
            for (int ni = 0; ni < 4; ni++)
                #pragma unroll
                for (int half = 0; half < 2; half++) {
                    int rl = mi * 16 + (lane >> 2) + 8 * half;
                    int c0 = ng * 32 + ni * 8 + 2 * (lane & 3);
                    size_t base = (size_t)(m0 + rl) * 256 + c0;
                    float m = mstat[rl], ir = rstat[rl];
                    float2 w1v = *(const float2*)(lnw1 + c0);
                    float2 b1v = *(const float2*)(lnb1 + c0);
                    float v0 = acc[mi][ni][half * 2 + 0];
                    float v1 = acc[mi][ni][half * 2 + 1];
                    float l0 = (v0 - m) * ir * w1v.x + b1v.x;
                    float l1 = (v1 - m) * ir * w1v.y + b1v.y;
                    float2 xr = *(const float2*)(resid1 + base);
                    float2 xsf = __half22float2(*(const __half2*)(resid2h + base));
                    float xv0 = xr.x + xsf.x + g * l0;
                    float xv1 = xr.y + xsf.y + g * l1;
                    *(__half2*)(outA + base) = __floats2half2_rn(xv0, xv1);
                    acc[mi][ni][half * 2 + 0] = xv0;
                    acc[mi][ni][half * 2 + 1] = xv1;
                }
        rowreduce();
        #pragma unroll
        for (int mi = 0; mi < 4; mi++)
            #pragma unroll
            for (int ni = 0; ni < 4; ni++)
                #pragma unroll
                for (int half = 0; half < 2; half++) {
                    int rl = mi * 16 + (lane >> 2) + 8 * half;
                    int c0 = ng * 32 + ni * 8 + 2 * (lane & 3);
                    size_t base = (size_t)(m0 + rl) * 256 + c0;
                    float m = mstat[rl], ir = rstat[rl];
                    float2 w2v = *(const float2*)(lnw2 + c0);
                    float2 b2v = *(const float2*)(lnb2 + c0);
                    float t0 = (acc[mi][ni][half * 2 + 0] - m) * ir * w2v.x + b2v.x;
                    float t1 = (acc[mi][ni][half * 2 + 1] - m) * ir * w2v.y + b2v.y;
                    *(__half2*)(out16 + base) = __floats2half2_rn(t0, t1);
                }
    } else {
        #pragma unroll
        for (int mi = 0; mi < 4; mi++)
            #pragma unroll
            for (int ni = 0; ni < 4; ni++)
                #pragma unroll
                for (int half = 0; half < 2; half++) {
                    int rl = mi * 16 + (lane >> 2) + 8 * half;
                    int c0 = ng * 32 + ni * 8 + 2 * (lane & 3);
                    size_t base = (size_t)(m0 + rl) * 256 + c0;
                    float2 xr = __half22float2(*(const __half2*)(resid2h + base));
                    float xv0 = 2.f * xr.x + g * acc[mi][ni][half * 2 + 0];
                    float xv1 = 2.f * xr.y + g * acc[mi][ni][half * 2 + 1];
                    *(__half2*)(outA + base) = __floats2half2_rn(xv0, xv1);
                    acc[mi][ni][half * 2 + 0] = xv0;
                    acc[mi][ni][half * 2 + 1] = xv1;
                }
        rowreduce();
        #pragma unroll
        for (int mi = 0; mi < 4; mi++)
            #pragma unroll
            for (int ni = 0; ni < 4; ni++)
                #pragma unroll
                for (int half = 0; half < 2; half++) {
                    int rl = mi * 16 + (lane >> 2) + 8 * half;
                    int c0 = ng * 32 + ni * 8 + 2 * (lane & 3);
                    size_t base = (size_t)(m0 + rl) * 256 + c0;
                    float m = mstat[rl], ir = rstat[rl];
                    float2 w1v = *(const float2*)(lnw1 + c0);
                    float2 b1v = *(const float2*)(lnb1 + c0);
                    float t0 = (acc[mi][ni][half * 2 + 0] - m) * ir * w1v.x + b1v.x;
                    float t1 = (acc[mi][ni][half * 2 + 1] - m) * ir * w1v.y + b1v.y;
                    *(__half2*)(out16 + base) = __floats2half2_rn(t0, t1);
                }
    }
}

// -------------------------------- launcher --------------------------------
template<typename T>
static T* symaddr(const void* sym)
{
    void* p = nullptr;
    cudaGetSymbolAddress(&p, sym);
    return (T*)p;
}

extern "C" void kernel_launch(void* const* d_in, const int* in_sizes, int n_in,
                              void* d_out, int out_size)
{
    const float* x       = (const float*)d_in[0];
    const int*   adj     = (const int*)  d_in[1];
    const float* n1_w    = (const float*)d_in[2];
    const float* n1_b    = (const float*)d_in[3];
    const float* q_w     = (const float*)d_in[4];
    const float* k_w     = (const float*)d_in[5];
    const float* v_w     = (const float*)d_in[6];
    const float* proj_w  = (const float*)d_in[7];
    const float* proj_b  = (const float*)d_in[8];
    const float* on_w    = (const float*)d_in[9];
    const float* on_b    = (const float*)d_in[10];
    const float* gamma_s = (const float*)d_in[11];
    const float* conv1_w = (const float*)d_in[12];
    const float* bn1_w   = (const float*)d_in[13];
    const float* bn1_b   = (const float*)d_in[14];
    const float* bn1_m   = (const float*)d_in[15];
    const float* bn1_v   = (const float*)d_in[16];
    const float* conv2_w = (const float*)d_in[17];
    const float* bn2_w   = (const float*)d_in[18];
    const float* bn2_b   = (const float*)d_in[19];
    const float* bn2_m   = (const float*)d_in[20];
    const float* bn2_v   = (const float*)d_in[21];
    const float* tn_w    = (const float*)d_in[22];
    const float* tn_b    = (const float*)d_in[23];
    const float* gamma_t = (const float*)d_in[24];
    const float* n3_w    = (const float*)d_in[25];
    const float* n3_b    = (const float*)d_in[26];
    const float* fc1_w   = (const float*)d_in[27];
    const float* fc1_b   = (const float*)d_in[28];
    const float* fc2_w   = (const float*)d_in[29];
    const float* fc2_b   = (const float*)d_in[30];
    float* out = (float*)d_out;

    __half* xs16 = symaddr<__half>(g_xs16);
    __half* qkvh = symaddr<__half>(g_qkvh);
    __half* o16  = symaddr<__half>(g_o16);
    __half* x1h  = symaddr<__half>(g_x1h);
    __half* xt16 = symaddr<__half>(g_xt16);
    __half* y1h  = symaddr<__half>(g_y1h);
    __half* x2h  = symaddr<__half>(g_x2h);
    __half* xm16 = symaddr<__half>(g_xm16);
    __half* bigh = symaddr<__half>(g_bigh);
    __half* hqkv = symaddr<__half>(g_hqkv);
    __half* hp   = symaddr<__half>(g_hp);
    __half* hw1  = symaddr<__half>(g_hw1);
    __half* hw2  = symaddr<__half>(g_hw2);
    __half* hf1  = symaddr<__half>(g_hf1);
    __half* hf2  = symaddr<__half>(g_hf2);
    float* bn1s = symaddr<float>(g_bn1s);
    float* bn1b = symaddr<float>(g_bn1b);
    float* bn2s = symaddr<float>(g_bn2s);
    float* bn2b = symaddr<float>(g_bn2b);

    cudaFuncSetAttribute(h_gemm<256,  false, true >, cudaFuncAttributeMaxDynamicSharedMemorySize, HG_SMEM);
    cudaFuncSetAttribute(h_gemm<768,  true,  true >, cudaFuncAttributeMaxDynamicSharedMemorySize, HG_SMEM);
    cudaFuncSetAttribute(h_gemm<1024, false, false>, cudaFuncAttributeMaxDynamicSharedMemorySize, HG_SMEM);
    cudaFuncSetAttribute(h_gemm_lnrow<256, true >, cudaFuncAttributeMaxDynamicSharedMemorySize, HGL_SMEM);
    cudaFuncSetAttribute(h_gemm_lnrow<512, false>, cudaFuncAttributeMaxDynamicSharedMemorySize, HGL_SMEM);
    cudaFuncSetAttribute(attn_mma, cudaFuncAttributeMaxDynamicSharedMemorySize, ATT_SMEM);

    // 0) merged prep + LN(x) -> xs16
    prep_ln_kernel<<<RROWS, 256>>>(x, n1_w, n1_b, xs16,
                                   q_w, k_w, v_w, proj_w, conv1_w, conv2_w, fc1_w, fc2_w,
                                   adj, bn1_w, bn1_b, bn1_m, bn1_v,
                                   bn2_w, bn2_b, bn2_m, bn2_v);

    // 1) fused QKV GEMM -> [R][768] fp16
    h_gemm<256, false, true><<<dim3(6, 512), 256, HG_SMEM>>>(xs16, hqkv, qkvh, 768,
        nullptr, nullptr, 0, nullptr, 0.f, nullptr);

    // 2) tensor-core masked attention (single wave)
    attn_mma<<<256, 256, ATT_SMEM>>>(qkvh, o16);

    // 3) proj GEMM + bias + LN + residual + LN -> x1 (fp16), xt16 (fp16)
    h_gemm_lnrow<256, true><<<dim3(1, 1024), 256, HGL_SMEM>>>(
        o16, hp, nullptr, proj_b, x, xs16, gamma_s,
        on_w, on_b, tn_w, tn_b, x1h, xt16);

    // 4) conv1 (gathered) + BN1 + GELU -> y1 fp16
    h_gemm<768, true, true><<<dim3(4, 512), 256, HG_SMEM>>>(xt16, hw1, y1h, HH2,
        bn1s, bn1b, 1, nullptr, 0.f, nullptr);

    // 5) conv2 GEMM + BN2 + (x2 = 2*x1 + gamma_t*y) + LN -> x2 (fp16), xm16
    h_gemm_lnrow<512, false><<<dim3(1, 1024), 256, HGL_SMEM>>>(
        y1h, hw2, bn2s, bn2b, nullptr, x1h, gamma_t,
        n3_w, n3_b, nullptr, nullptr, x2h, xm16);

    // 6) fc1 + bias + GELU -> big fp16
    h_gemm<256, false, true><<<dim3(8, 512), 256, HG_SMEM>>>(xm16, hf1, bigh, MM,
        nullptr, fc1_b, 1, nullptr, 0.f, nullptr);

    // 7) fc2 + bias + residual x2 (fp16) -> out fp32
    h_gemm<1024, false, false><<<dim3(2, 512), 256, HG_SMEM>>>(bigh, hf2, out, CC,
        nullptr, fc2_b, 0, x2h, 1.0f, nullptr);
}

// round 17
// speedup vs baseline: 1.1299x; 1.0838x over previous
#include <cuda_runtime.h>
#include <cuda_fp16.h>
#include <cstdint>
#include <math.h>

// ---------------- problem constants ----------------
#define BB 8
#define TT 64
#define EE 128
#define CC 256
#define HH2 512          // conv hidden
#define MM 1024          // mlp hidden
#define RROWS 65536      // B*T*E
#define LNEPS 1e-5f

// ---------------- device scratch ----------------
__device__ __align__(128) __half g_xs16[RROWS * CC];    // xs fp16
__device__ __align__(128) __half g_xpx16[RROWS * CC];   // x + xs fp16
__device__ __align__(128) __half g_qkvh[RROWS * 768];   // q|k|v fp16
__device__ __align__(128) __half g_o16 [RROWS * CC];    // attn out fp16
__device__ __align__(128) __half g_x1h [RROWS * CC];    // x1 fp16
__device__ __align__(128) __half g_xt16[RROWS * CC];    // LN(x1) fp16
__device__ __align__(128) __half g_y1h [RROWS * HH2];   // conv1 out fp16
__device__ __align__(128) __half g_x2h [RROWS * CC];    // x2 fp16
__device__ __align__(128) __half g_xm16[RROWS * CC];    // LN(x2) fp16
__device__ __align__(128) __half g_bigh[RROWS * MM];    // mlp hidden fp16
// fp16 weights, all [N][K] K-major
__device__ __align__(128) __half g_hqkv[768 * CC];
__device__ __align__(128) __half g_hp  [CC * CC];
__device__ __align__(128) __half g_hw1 [HH2 * 768];     // conv1: [h][kk], kk=j*256+c
__device__ __align__(128) __half g_hw2 [CC * HH2];
__device__ __align__(128) __half g_hf1 [MM * CC];
__device__ __align__(128) __half g_hf2 [CC * MM];
__device__ __align__(128) float g_maskf[EE * EE];       // 0.5 * adj_mask
__device__ __align__(128) float g_bn1s[HH2], g_bn1b[HH2], g_bn2s[CC], g_bn2b[CC];

// ---------------- helpers ----------------
__device__ __forceinline__ uint32_t smem_u32(const void* p)
{
    uint32_t a;
    asm("{ .reg .u64 t; cvta.to.shared.u64 t, %1; cvt.u32.u64 %0, t; }" : "=r"(a) : "l"(p));
    return a;
}
__device__ __forceinline__ void mma16(float* d, const uint4& a, const uint2& b)
{
    asm volatile("mma.sync.aligned.m16n8k16.row.col.f32.f16.f16.f32 "
                 "{%0,%1,%2,%3}, {%4,%5,%6,%7}, {%8,%9}, {%0,%1,%2,%3};"
                 : "+f"(d[0]), "+f"(d[1]), "+f"(d[2]), "+f"(d[3])
                 : "r"(a.x), "r"(a.y), "r"(a.z), "r"(a.w), "r"(b.x), "r"(b.y));
}
__device__ __forceinline__ uint4 ldsm4(uint32_t addr)
{
    uint4 r;
    asm volatile("ldmatrix.sync.aligned.m8n8.x4.shared.b16 {%0,%1,%2,%3}, [%4];"
                 : "=r"(r.x), "=r"(r.y), "=r"(r.z), "=r"(r.w) : "r"(addr));
    return r;
}
__device__ __forceinline__ void cpa16(uint32_t dst, const void* src)
{
    asm volatile("cp.async.cg.shared.global [%0], [%1], 16;" :: "r"(dst), "l"(src));
}
__device__ __forceinline__ void cpa16z(uint32_t dst, const void* src, int srcsize)
{
    asm volatile("cp.async.cg.shared.global [%0], [%1], 16, %2;"
                 :: "r"(dst), "l"(src), "r"(srcsize));
}
#define CP_COMMIT() asm volatile("cp.async.commit_group;" ::: "memory")
#define CP_WAIT2()  asm volatile("cp.async.wait_group 2;" ::: "memory")

__device__ __forceinline__ float gelu_exact(float v)
{
    return 0.5f * v * (1.f + erff(v * 0.70710678118654752f));
}

// ---------------- merged prep + warp-per-row LN(x) -----------------------------
// grid 8192 x 256: warp j of block b handles row b*8+j (pure shfl reduce, no bars)
// Outputs: xs16 = LN(x), xpx16 = half(x + LN(x)).
__global__ void prep_ln_kernel(const float* __restrict__ x,
                               const float* __restrict__ n1w, const float* __restrict__ n1b,
                               __half* __restrict__ xs16, __half* __restrict__ xpx16,
                               const float* __restrict__ qw, const float* __restrict__ kw,
                               const float* __restrict__ vw, const float* __restrict__ pw,
                               const float* __restrict__ w1, const float* __restrict__ w2,
                               const float* __restrict__ f1, const float* __restrict__ f2,
                               const int* __restrict__ mask,
                               const float* __restrict__ b1w, const float* __restrict__ b1b,
                               const float* __restrict__ b1m, const float* __restrict__ b1v,
                               const float* __restrict__ b2w, const float* __restrict__ b2b,
                               const float* __restrict__ b2m, const float* __restrict__ b2v)
{
    int tid = threadIdx.x;
    // ---- prep portion (idx-guarded; 8192*256 = 2M threads covers all) ----
    int idx = blockIdx.x * 256 + tid;
    if (idx < 768 * CC) {
        int n = idx >> 8, k = idx & 255;
        const float* src = (n < 256) ? qw : (n < 512) ? kw : vw;
        g_hqkv[idx] = __float2half(src[k * CC + (n & 255)]);
    }
    if (idx < CC * CC) {
        int n = idx >> 8, k = idx & 255;
        g_hp[idx] = __float2half(pw[k * CC + n]);
    }
    if (idx < HH2 * 768) {
        int h = idx / 768, kk = idx % 768;
        int j = kk >> 8, c = kk & 255;
        g_hw1[idx] = __float2half(w1[h * 768 + c * 3 + j]);
    }
    if (idx < CC * HH2) g_hw2[idx] = __float2half(w2[idx]);
    if (idx < MM * CC) {
        int n = idx >> 8, k = idx & 255;
        g_hf1[idx] = __float2half(f1[k * MM + n]);
    }
    if (idx < CC * MM) {
        int n = idx >> 10, k = idx & 1023;
        g_hf2[idx] = __float2half(f2[k * CC + n]);
    }
    if (idx < EE * EE) g_maskf[idx] = 0.5f * (float)mask[idx];
    if (idx < HH2) {
        float s = b1w[idx] * rsqrtf(b1v[idx] + LNEPS);
        g_bn1s[idx] = s;
        g_bn1b[idx] = b1b[idx] - b1m[idx] * s;
    }
    if (idx < CC) {
        float s = b2w[idx] * rsqrtf(b2v[idx] + LNEPS);
        g_bn2s[idx] = s;
        g_bn2b[idx] = b2b[idx] - b2m[idx] * s;
    }

    // ---- warp-per-row LN ----
    int lane = tid & 31;
    size_t row = (size_t)blockIdx.x * 8 + (tid >> 5);
    const float* xr = x + row * CC + lane * 8;
    float4 a0 = *(const float4*)(xr);
    float4 a1 = *(const float4*)(xr + 4);
    float v[8] = {a0.x, a0.y, a0.z, a0.w, a1.x, a1.y, a1.z, a1.w};
    float s = 0.f, q = 0.f;
    #pragma unroll
    for (int i = 0; i < 8; i++) { s += v[i]; q += v[i] * v[i]; }
    #pragma unroll
    for (int o = 16; o; o >>= 1) {
        s += __shfl_xor_sync(0xffffffffu, s, o);
        q += __shfl_xor_sync(0xffffffffu, q, o);
    }
    float mean = s * (1.f / CC);
    float rstd = rsqrtf(q * (1.f / CC) - mean * mean + LNEPS);
    float4 wA = *(const float4*)(n1w + lane * 8);
    float4 wB = *(const float4*)(n1w + lane * 8 + 4);
    float4 bA = *(const float4*)(n1b + lane * 8);
    float4 bB = *(const float4*)(n1b + lane * 8 + 4);
    float wv[8] = {wA.x, wA.y, wA.z, wA.w, wB.x, wB.y, wB.z, wB.w};
    float bvv[8] = {bA.x, bA.y, bA.z, bA.w, bB.x, bB.y, bB.z, bB.w};
    __half hs[8], hp2[8];
    #pragma unroll
    for (int i = 0; i < 8; i++) {
        float ln = (v[i] - mean) * rstd * wv[i] + bvv[i];
        hs[i]  = __float2half(ln);
        hp2[i] = __float2half(v[i] + ln);
    }
    *(uint4*)(xs16  + row * CC + lane * 8) = *(uint4*)hs;
    *(uint4*)(xpx16 + row * CC + lane * 8) = *(uint4*)hp2;
}

// ---------------- tensor-core attention (verified): 2 bt per CTA ---------------
#define MSTR 136
#define QSTR 40
#define VSTR 136
static constexpr int ATT_SMEM = 64000;

__global__ void __launch_bounds__(256, 2) attn_mma(const __half* __restrict__ QKV,
                                                   __half* __restrict__ O)
{
    extern __shared__ __align__(128) __half sm[];
    __half* maskS = sm;
    __half* Qs = sm + 17408;
    __half* Ks = Qs + 5120;
    __half* Vt = Ks + 5120;
    const int tid = threadIdx.x, w = tid >> 5, lane = tid & 31;
    const int r = lane >> 2, c = lane & 3;
    const int eBase = w * 16;

    for (int i = tid; i < 128 * 32; i += 256) {
        int e = i >> 5, f4 = (i & 31) * 4;
        float4 mv = *(const float4*)&g_maskf[e * 128 + f4];
        __half2 h0 = __floats2half2_rn(mv.x, mv.y);
        __half2 h1 = __floats2half2_rn(mv.z, mv.w);
        *(uint2*)&maskS[e * MSTR + f4] = make_uint2(*(uint32_t*)&h0, *(uint32_t*)&h1);
    }
    __syncthreads();

    const int se = tid >> 1, sp = tid & 1;

    #pragma unroll 1
    for (int bt = blockIdx.x; bt < BB * TT; bt += 256) {
        const __half* qbase = QKV + (size_t)bt * 128 * 768;
        for (int h = 0; h < 8; h++) {
            {
                const __half* row = qbase + (size_t)se * 768 + h * 32 + sp * 16;
                uint4 q0 = *(const uint4*)(row);
                uint4 q1 = *(const uint4*)(row + 8);
                *(uint4*)&Qs[se * QSTR + sp * 16]     = q0;
                *(uint4*)&Qs[se * QSTR + sp * 16 + 8] = q1;
                uint4 k0 = *(const uint4*)(row + 256);
                uint4 k1 = *(const uint4*)(row + 264);
                *(uint4*)&Ks[se * QSTR + sp * 16]     = k0;
                *(uint4*)&Ks[se * QSTR + sp * 16 + 8] = k1;
                uint4 v0 = *(const uint4*)(row + 512);
                uint4 v1 = *(const uint4*)(row + 520);
                const __half* vh0 = (const __half*)&v0;
                const __half* vh1 = (const __half*)&v1;
                #pragma unroll
                for (int i = 0; i < 8; i++) {
                    Vt[(sp * 16 + i) * VSTR + se]     = vh0[i];
                    Vt[(sp * 16 + 8 + i) * VSTR + se] = vh1[i];
                }
            }
            __syncthreads();

            uint4 aQ[2];
            #pragma unroll
            for (int ks = 0; ks < 2; ks++) {
                const __half* q0 = &Qs[(eBase + r) * QSTR + ks * 16 + 2 * c];
                aQ[ks].x = *(const uint32_t*)q0;
                aQ[ks].y = *(const uint32_t*)(q0 + 8 * QSTR);
                aQ[ks].z = *(const uint32_t*)(q0 + 8);
                aQ[ks].w = *(const uint32_t*)(q0 + 8 * QSTR + 8);
            }

            float oacc[4][4] = {};
            #pragma unroll
            for (int ph = 0; ph < 2; ph++) {
                float sacc[8][4] = {};
                #pragma unroll
                for (int nt = 0; nt < 8; nt++) {
                    const __half* kp = &Ks[(ph * 64 + nt * 8 + r) * QSTR + 2 * c];
                    #pragma unroll
                    for (int ks = 0; ks < 2; ks++) {
                        uint2 bf;
                        bf.x = *(const uint32_t*)(kp + ks * 16);
                        bf.y = *(const uint32_t*)(kp + ks * 16 + 8);
                        mma16(sacc[nt], aQ[ks], bf);
                    }
                }
                uint32_t wh[8][2];
                #pragma unroll
                for (int nt = 0; nt < 8; nt++) {
                    int fb = ph * 64 + nt * 8 + 2 * c;
                    float2 m0 = __half22float2(*(__half2*)&maskS[(eBase + r) * MSTR + fb]);
                    float2 m1 = __half22float2(*(__half2*)&maskS[(eBase + r + 8) * MSTR + fb]);
                    __half2 w0 = __floats2half2_rn(sacc[nt][0] * m0.x + 0.5f,
                                                   sacc[nt][1] * m0.y + 0.5f);
                    __half2 w1 = __floats2half2_rn(sacc[nt][2] * m1.x + 0.5f,
                                                   sacc[nt][3] * m1.y + 0.5f);
                    wh[nt][0] = *(uint32_t*)&w0;
                    wh[nt][1] = *(uint32_t*)&w1;
                }
                #pragma unroll
                for (int kk = 0; kk < 4; kk++) {
                    uint4 aw = make_uint4(wh[2 * kk][0], wh[2 * kk][1],
                                          wh[2 * kk + 1][0], wh[2 * kk + 1][1]);
                    #pragma unroll
                    for (int dt = 0; dt < 4; dt++) {
                        const __half* vp = &Vt[(dt * 8 + r) * VSTR + ph * 64 + kk * 16 + 2 * c];
                        uint2 bf;
                        bf.x = *(const uint32_t*)vp;
                        bf.y = *(const uint32_t*)(vp + 8);
                        mma16(oacc[dt], aw, bf);
                    }
                }
            }
            size_t ob = ((size_t)bt * 128 + eBase + r) * 256 + h * 32;
            #pragma unroll
            for (int dt = 0; dt < 4; dt++) {
                __half2 o0 = __floats2half2_rn(oacc[dt][0], oacc[dt][1]);
                __half2 o1 = __floats2half2_rn(oacc[dt][2], oacc[dt][3]);
                *(uint32_t*)&O[ob + dt * 8 + 2 * c]           = *(uint32_t*)&o0;
                *(uint32_t*)&O[ob + 8 * 256 + dt * 8 + 2 * c] = *(uint32_t*)&o1;
            }
            __syncthreads();
        }
    }
}

// ---------------- fp16 GEMM (verified); fp16 residual --------------------------
static constexpr int HG_SMEM = 65536;

template<int KDIM, bool GATHER, bool OUTH>
__global__ void __launch_bounds__(256, 2) h_gemm(
        const __half* __restrict__ A, const __half* __restrict__ Bt,
        void* __restrict__ Cv, int N,
        const float* __restrict__ colScale, const float* __restrict__ colShift,
        int doGelu, const __half* __restrict__ res, float resCoef,
        const float* __restrict__ vMul)
{
    extern __shared__ __align__(128) char smem[];
    constexpr int NT = KDIM / 32;
    const int tid = threadIdx.x;
    const int w = tid >> 5, lane = tid & 31;
    const int n0 = blockIdx.x * 128, m0 = blockIdx.y * 128;
    const int mg = w >> 2, ng = w & 3;
    const uint32_t sbase = smem_u32(smem);

    float acc[4][4][4] = {};

    auto produce = [&](int stg, int kt) {
        uint32_t sb = sbase + stg * 16384;
        #pragma unroll
        for (int it = 0; it < 2; it++) {
            int id = tid + it * 256;
            int row = id >> 2, c = id & 3;
            uint32_t swoff = (uint32_t)((c ^ ((row >> 1) & 3)) * 16);
            uint32_t dstA = sb + row * 64 + swoff;
            if (GATHER) {
                int kg = kt * 32 + c * 8;
                int j = kg >> 8, cc = kg & 255;
                int t = ((m0 + row) >> 7) & 63;
                int tt = t + j - 1;
                bool valid = (unsigned)tt < 64u;
                const __half* src = A + ((size_t)(m0 + row) + (ptrdiff_t)(j - 1) * EE) * CC + cc;
                cpa16z(dstA, valid ? src : (const __half*)A, valid ? 16 : 0);
            } else {
                cpa16(dstA, A + (size_t)(m0 + row) * KDIM + kt * 32 + c * 8);
            }
            cpa16(sb + 8192 + row * 64 + swoff,
                  Bt + (size_t)(n0 + row) * KDIM + kt * 32 + c * 8);
        }
    };
    auto compute = [&](int stg) {
        uint32_t sb = sbase + stg * 16384;
        uint4 af[2][4];
        uint2 bf[2][4];
        #pragma unroll
        for (int ks = 0; ks < 2; ks++)
            #pragma unroll
            for (int mi = 0; mi < 4; mi++) {
                int row = mg * 64 + mi * 16 + (lane & 15);
                int ch = (ks * 2 + (lane >> 4)) ^ ((row >> 1) & 3);
                af[ks][mi] = ldsm4(sb + row * 64 + ch * 16);
            }
        #pragma unroll
        for (int ks = 0; ks < 2; ks++)
            #pragma unroll
            for (int p = 0; p < 2; p++) {
                int ni = 2 * p + (lane >> 4);
                int row = ng * 32 + ni * 8 + (lane & 7);
                int ch = (ks * 2 + ((lane >> 3) & 1)) ^ ((row >> 1) & 3);
                uint4 t4 = ldsm4(sb + 8192 + row * 64 + ch * 16);
                bf[ks][2 * p]     = make_uint2(t4.x, t4.y);
                bf[ks][2 * p + 1] = make_uint2(t4.z, t4.w);
            }
        #pragma unroll
        for (int ks = 0; ks < 2; ks++)
            #pragma unroll
            for (int mi = 0; mi < 4; mi++)
                #pragma unroll
                for (int ni = 0; ni < 4; ni++)
                    mma16(acc[mi][ni], af[ks][mi], bf[ks][ni]);
    };

    #pragma unroll
    for (int s = 0; s < 3; s++) {
        if (s < NT) produce(s, s);
        CP_COMMIT();
    }
    #pragma unroll 1
    for (int kt = 0; kt < NT; kt++) {
        CP_WAIT2();
        __syncthreads();
        if (kt + 3 < NT) produce((kt + 3) & 3, kt + 3);
        CP_COMMIT();
        compute(kt & 3);
    }

    const float vm = vMul ? *vMul : 1.0f;
    #pragma unroll
    for (int mi = 0; mi < 4; mi++) {
        #pragma unroll
        for (int ni = 0; ni < 4; ni++) {
            int r0 = m0 + (mg * 4 + mi) * 16 + (lane >> 2);
            int c0 = n0 + (ng * 4 + ni) * 8 + 2 * (lane & 3);
            #pragma unroll
            for (int half = 0; half < 2; half++) {
                int row = r0 + half * 8;
                float v0 = acc[mi][ni][half * 2 + 0];
                float v1 = acc[mi][ni][half * 2 + 1];
                size_t base = (size_t)row * N + c0;
                if (colScale) {
                    v0 = v0 * colScale[c0] + colShift[c0];
                    v1 = v1 * colScale[c0 + 1] + colShift[c0 + 1];
                } else if (colShift) {
                    v0 += colShift[c0];
                    v1 += colShift[c0 + 1];
                }
                if (doGelu) { v0 = gelu_exact(v0); v1 = gelu_exact(v1); }
                if (res) {
                    float2 r2 = __half22float2(*(const __half2*)(res + base));
                    v0 = resCoef * r2.x + vm * v0;
                    v1 = resCoef * r2.y + vm * v1;
                }
                if (OUTH) {
                    __half2 h2v = __floats2half2_rn(v0, v1);
                    *(__half2*)((__half*)Cv + base) = h2v;
                } else {
                    *(float2*)((float*)Cv + base) = make_float2(v0, v1);
                }
            }
        }
    }
}

// ---------------- GEMM + fused row-LN epilogue; fp16 in/out --------------------
static constexpr int HGL_SMEM = 4 * 20480 + 4096 + 512;

template<int KDIM, bool DUAL>
__global__ void __launch_bounds__(256, 2) h_gemm_lnrow(
        const __half* __restrict__ A, const __half* __restrict__ Bt,
        const float* __restrict__ colScale, const float* __restrict__ colShift,
        const __half* __restrict__ resid2h,
        const float* __restrict__ gamma,
        const float* __restrict__ lnw1, const float* __restrict__ lnb1,
        const float* __restrict__ lnw2, const float* __restrict__ lnb2,
        __half* __restrict__ outA, __half* __restrict__ out16)
{
    extern __shared__ __align__(128) char smem[];
    constexpr int NT = KDIM / 32;
    const int tid = threadIdx.x;
    const int wp = tid >> 5, lane = tid & 31;
    const int m0 = blockIdx.y * 64;
    const int ng = wp;
    const uint32_t sbase = smem_u32(smem);
    float* ps    = (float*)(smem + 81920);
    float* pq    = ps + 512;
    float* mstat = pq + 512;
    float* rstat = mstat + 64;

    float acc[4][4][4] = {};

    auto produce = [&](int stg, int kt) {
        uint32_t sb = sbase + stg * 20480;
        {
            int row = tid >> 2, c = tid & 3;
            uint32_t swoff = (uint32_t)((c ^ ((row >> 1) & 3)) * 16);
            cpa16(sb + row * 64 + swoff, A + (size_t)(m0 + row) * KDIM + kt * 32 + c * 8);
        }
        #pragma unroll
        for (int it = 0; it < 4; it++) {
            int id = tid + it * 256;
            int row = id >> 2, c = id & 3;
            uint32_t swoff = (uint32_t)((c ^ ((row >> 1) & 3)) * 16);
            cpa16(sb + 4096 + row * 64 + swoff, Bt + (size_t)row * KDIM + kt * 32 + c * 8);
        }
    };
    auto compute = [&](int stg) {
        uint32_t sb = sbase + stg * 20480;
        uint4 af[2][4];
        uint2 bf[2][4];
        #pragma unroll
        for (int ks = 0; ks < 2; ks++)
            #pragma unroll
            for (int mi = 0; mi < 4; mi++) {
                int row = mi * 16 + (lane & 15);
                int ch = (ks * 2 + (lane >> 4)) ^ ((row >> 1) & 3);
                af[ks][mi] = ldsm4(sb + row * 64 + ch * 16);
            }
        #pragma unroll
        for (int ks = 0; ks < 2; ks++)
            #pragma unroll
            for (int p = 0; p < 2; p++) {
                int ni = 2 * p + (lane >> 4);
                int row = ng * 32 + ni * 8 + (lane & 7);
                int ch = (ks * 2 + ((lane >> 3) & 1)) ^ ((row >> 1) & 3);
                uint4 t4 = ldsm4(sb + 4096 + row * 64 + ch * 16);
                bf[ks][2 * p]     = make_uint2(t4.x, t4.y);
                bf[ks][2 * p + 1] = make_uint2(t4.z, t4.w);
            }
        #pragma unroll
        for (int ks = 0; ks < 2; ks++)
            #pragma unroll
            for (int mi = 0; mi < 4; mi++)
                #pragma unroll
                for (int ni = 0; ni < 4; ni++)
                    mma16(acc[mi][ni], af[ks][mi], bf[ks][ni]);
    };

    #pragma unroll
    for (int s = 0; s < 3; s++) {
        if (s < NT) produce(s, s);
        CP_COMMIT();
    }
    #pragma unroll 1
    for (int kt = 0; kt < NT; kt++) {
        CP_WAIT2();
        __syncthreads();
        if (kt + 3 < NT) produce((kt + 3) & 3, kt + 3);
        CP_COMMIT();
        compute(kt & 3);
    }

    auto rowreduce = [&]() {
        #pragma unroll
        for (int mi = 0; mi < 4; mi++) {
            #pragma unroll
            for (int half = 0; half < 2; half++) {
                float s = 0.f, q2 = 0.f;
                #pragma unroll
                for (int ni = 0; ni < 4; ni++) {
                    float a0 = acc[mi][ni][half * 2 + 0];
                    float a1 = acc[mi][ni][half * 2 + 1];
                    s  += a0 + a1;
                    q2 += a0 * a0 + a1 * a1;
                }
                #pragma unroll
                for (int o = 1; o <= 2; o <<= 1) {
                    s  += __shfl_xor_sync(0xffffffffu, s,  o);
                    q2 += __shfl_xor_sync(0xffffffffu, q2, o);
                }
                if ((lane & 3) == 0) {
                    int r = mi * 16 + 8 * half + (lane >> 2);
                    ps[wp * 64 + r] = s;
                    pq[wp * 64 + r] = q2;
                }
            }
        }
        __syncthreads();
        if (tid < 64) {
            float S = 0.f, Q = 0.f;
            #pragma unroll
            for (int w8 = 0; w8 < 8; w8++) { S += ps[w8 * 64 + tid]; Q += pq[w8 * 64 + tid]; }
            float m = S * (1.f / 256.f);
            mstat[tid] = m;
            rstat[tid] = rsqrtf(Q * (1.f / 256.f) - m * m + LNEPS);
        }
        __syncthreads();
    };

    const float g = gamma[0];

    #pragma unroll
    for (int mi = 0; mi < 4; mi++)
        #pragma unroll
        for (int ni = 0; ni < 4; ni++)
            #pragma unroll
            for (int half = 0; half < 2; half++) {
                int c0 = ng * 32 + ni * 8 + 2 * (lane & 3);
                if (DUAL) {
                    acc[mi][ni][half * 2 + 0] += colShift[c0];
                    acc[mi][ni][half * 2 + 1] += colShift[c0 + 1];
                } else {
                    acc[mi][ni][half * 2 + 0] = acc[mi][ni][half * 2 + 0] * colScale[c0] + colShift[c0];
                    acc[mi][ni][half * 2 + 1] = acc[mi][ni][half * 2 + 1] * colScale[c0 + 1] + colShift[c0 + 1];
                }
            }

    if (DUAL) {
        rowreduce();
        #pragma unroll
        for (int mi = 0; mi < 4; mi++)
            #pragma unroll
            for (int ni = 0; ni < 4; ni++)
                #pragma unroll
                for (int half = 0; half < 2; half++) {
                    int rl = mi * 16 + (lane >> 2) + 8 * half;
                    int c0 = ng * 32 + ni * 8 + 2 * (lane & 3);
                    size_t base = (size_t)(m0 + rl) * 256 + c0;
                    float m = mstat[rl], ir = rstat[rl];
                    float2 w1v = *(const float2*)(lnw1 + c0);
                    float2 b1vv = *(const float2*)(lnb1 + c0);
                    float v0 = acc[mi][ni][half * 2 + 0];
                    float v1 = acc[mi][ni][half * 2 + 1];
                    float l0 = (v0 - m) * ir * w1v.x + b1vv.x;
                    float l1 = (v1 - m) * ir * w1v.y + b1vv.y;
                    float2 xp = __half22float2(*(const __half2*)(resid2h + base));
                    float xv0 = xp.x + g * l0;
                    float xv1 = xp.y + g * l1;
                    *(__half2*)(outA + base) = __floats2half2_rn(xv0, xv1);
                    acc[mi][ni][half * 2 + 0] = xv0;
                    acc[mi][ni][half * 2 + 1] = xv1;
                }
        rowreduce();
        #pragma unroll
        for (int mi = 0; mi < 4; mi++)
            #pragma unroll
            for (int ni = 0; ni < 4; ni++)
                #pragma unroll
                for (int half = 0; half < 2; half++) {
                    int rl = mi * 16 + (lane >> 2) + 8 * half;
                    int c0 = ng * 32 + ni * 8 + 2 * (lane & 3);
                    size_t base = (size_t)(m0 + rl) * 256 + c0;
                    float m = mstat[rl], ir = rstat[rl];
                    float2 w2v = *(const float2*)(lnw2 + c0);
                    float2 b2vv = *(const float2*)(lnb2 + c0);
                    float t0 = (acc[mi][ni][half * 2 + 0] - m) * ir * w2v.x + b2vv.x;
                    float t1 = (acc[mi][ni][half * 2 + 1] - m) * ir * w2v.y + b2vv.y;
                    *(__half2*)(out16 + base) = __floats2half2_rn(t0, t1);
                }
    } else {
        #pragma unroll
        for (int mi = 0; mi < 4; mi++)
            #pragma unroll
            for (int ni = 0; ni < 4; ni++)
                #pragma unroll
                for (int half = 0; half < 2; half++) {
                    int rl = mi * 16 + (lane >> 2) + 8 * half;
                    int c0 = ng * 32 + ni * 8 + 2 * (lane & 3);
                    size_t base = (size_t)(m0 + rl) * 256 + c0;
                    float2 xr = __half22float2(*(const __half2*)(resid2h + base));
                    float xv0 = 2.f * xr.x + g * acc[mi][ni][half * 2 + 0];
                    float xv1 = 2.f * xr.y + g * acc[mi][ni][half * 2 + 1];
                    *(__half2*)(outA + base) = __floats2half2_rn(xv0, xv1);
                    acc[mi][ni][half * 2 + 0] = xv0;
                    acc[mi][ni][half * 2 + 1] = xv1;
                }
        rowreduce();
        #pragma unroll
        for (int mi = 0; mi < 4; mi++)
            #pragma unroll
            for (int ni = 0; ni < 4; ni++)
                #pragma unroll
                for (int half = 0; half < 2; half++) {
                    int rl = mi * 16 + (lane >> 2) + 8 * half;
                    int c0 = ng * 32 + ni * 8 + 2 * (lane & 3);
                    size_t base = (size_t)(m0 + rl) * 256 + c0;
                    float m = mstat[rl], ir = rstat[rl];
                    float2 w1v = *(const float2*)(lnw1 + c0);
                    float2 b1vv = *(const float2*)(lnb1 + c0);
                    float t0 = (acc[mi][ni][half * 2 + 0] - m) * ir * w1v.x + b1vv.x;
                    float t1 = (acc[mi][ni][half * 2 + 1] - m) * ir * w1v.y + b1vv.y;
                    *(__half2*)(out16 + base) = __floats2half2_rn(t0, t1);
                }
    }
}

// -------------------------------- launcher --------------------------------
template<typename T>
static T* symaddr(const void* sym)
{
    void* p = nullptr;
    cudaGetSymbolAddress(&p, sym);
    return (T*)p;
}

extern "C" void kernel_launch(void* const* d_in, const int* in_sizes, int n_in,
                              void* d_out, int out_size)
{
    const float* x       = (const float*)d_in[0];
    const int*   adj     = (const int*)  d_in[1];
    const float* n1_w    = (const float*)d_in[2];
    const float* n1_b    = (const float*)d_in[3];
    const float* q_w     = (const float*)d_in[4];
    const float* k_w     = (const float*)d_in[5];
    const float* v_w     = (const float*)d_in[6];
    const float* proj_w  = (const float*)d_in[7];
    const float* proj_b  = (const float*)d_in[8];
    const float* on_w    = (const float*)d_in[9];
    const float* on_b    = (const float*)d_in[10];
    const float* gamma_s = (const float*)d_in[11];
    const float* conv1_w = (const float*)d_in[12];
    const float* bn1_w   = (const float*)d_in[13];
    const float* bn1_b   = (const float*)d_in[14];
    const float* bn1_m   = (const float*)d_in[15];
    const float* bn1_v   = (const float*)d_in[16];
    const float* conv2_w = (const float*)d_in[17];
    const float* bn2_w   = (const float*)d_in[18];
    const float* bn2_b   = (const float*)d_in[19];
    const float* bn2_m   = (const float*)d_in[20];
    const float* bn2_v   = (const float*)d_in[21];
    const float* tn_w    = (const float*)d_in[22];
    const float* tn_b    = (const float*)d_in[23];
    const float* gamma_t = (const float*)d_in[24];
    const float* n3_w    = (const float*)d_in[25];
    const float* n3_b    = (const float*)d_in[26];
    const float* fc1_w   = (const float*)d_in[27];
    const float* fc1_b   = (const float*)d_in[28];
    const float* fc2_w   = (const float*)d_in[29];
    const float* fc2_b   = (const float*)d_in[30];
    float* out = (float*)d_out;

    __half* xs16  = symaddr<__half>(g_xs16);
    __half* xpx16 = symaddr<__half>(g_xpx16);
    __half* qkvh  = symaddr<__half>(g_qkvh);
    __half* o16   = symaddr<__half>(g_o16);
    __half* x1h   = symaddr<__half>(g_x1h);
    __half* xt16  = symaddr<__half>(g_xt16);
    __half* y1h   = symaddr<__half>(g_y1h);
    __half* x2h   = symaddr<__half>(g_x2h);
    __half* xm16  = symaddr<__half>(g_xm16);
    __half* bigh  = symaddr<__half>(g_bigh);
    __half* hqkv  = symaddr<__half>(g_hqkv);
    __half* hp    = symaddr<__half>(g_hp);
    __half* hw1   = symaddr<__half>(g_hw1);
    __half* hw2   = symaddr<__half>(g_hw2);
    __half* hf1   = symaddr<__half>(g_hf1);
    __half* hf2   = symaddr<__half>(g_hf2);
    float* bn1s = symaddr<float>(g_bn1s);
    float* bn1b = symaddr<float>(g_bn1b);
    float* bn2s = symaddr<float>(g_bn2s);
    float* bn2b = symaddr<float>(g_bn2b);

    cudaFuncSetAttribute(h_gemm<256,  false, true >, cudaFuncAttributeMaxDynamicSharedMemorySize, HG_SMEM);
    cudaFuncSetAttribute(h_gemm<768,  true,  true >, cudaFuncAttributeMaxDynamicSharedMemorySize, HG_SMEM);
    cudaFuncSetAttribute(h_gemm<1024, false, false>, cudaFuncAttributeMaxDynamicSharedMemorySize, HG_SMEM);
    cudaFuncSetAttribute(h_gemm_lnrow<256, true >, cudaFuncAttributeMaxDynamicSharedMemorySize, HGL_SMEM);
    cudaFuncSetAttribute(h_gemm_lnrow<512, false>, cudaFuncAttributeMaxDynamicSharedMemorySize, HGL_SMEM);
    cudaFuncSetAttribute(attn_mma, cudaFuncAttributeMaxDynamicSharedMemorySize, ATT_SMEM);

    // 0) merged prep + warp-LN(x) -> xs16, xpx16
    prep_ln_kernel<<<RROWS / 8, 256>>>(x, n1_w, n1_b, xs16, xpx16,
                                       q_w, k_w, v_w, proj_w, conv1_w, conv2_w, fc1_w, fc2_w,
                                       adj, bn1_w, bn1_b, bn1_m, bn1_v,
                                       bn2_w, bn2_b, bn2_m, bn2_v);

    // 1) fused QKV GEMM -> [R][768] fp16
    h_gemm<256, false, true><<<dim3(6, 512), 256, HG_SMEM>>>(xs16, hqkv, qkvh, 768,
        nullptr, nullptr, 0, nullptr, 0.f, nullptr);

    // 2) tensor-core masked attention (single wave)
    attn_mma<<<256, 256, ATT_SMEM>>>(qkvh, o16);

    // 3) proj GEMM + bias + LN + residual(x+xs fp16) + LN -> x1h, xt16
    h_gemm_lnrow<256, true><<<dim3(1, 1024), 256, HGL_SMEM>>>(
        o16, hp, nullptr, proj_b, xpx16, gamma_s,
        on_w, on_b, tn_w, tn_b, x1h, xt16);

    // 4) conv1 (gathered) + BN1 + GELU -> y1 fp16
    h_gemm<768, true, true><<<dim3(4, 512), 256, HG_SMEM>>>(xt16, hw1, y1h, HH2,
        bn1s, bn1b, 1, nullptr, 0.f, nullptr);

    // 5) conv2 GEMM + BN2 + (x2 = 2*x1 + gamma_t*y) + LN -> x2h, xm16
    h_gemm_lnrow<512, false><<<dim3(1, 1024), 256, HGL_SMEM>>>(
        y1h, hw2, bn2s, bn2b, x1h, gamma_t,
        n3_w, n3_b, nullptr, nullptr, x2h, xm16);

    // 6) fc1 + bias + GELU -> big fp16
    h_gemm<256, false, true><<<dim3(8, 512), 256, HG_SMEM>>>(xm16, hf1, bigh, MM,
        nullptr, fc1_b, 1, nullptr, 0.f, nullptr);

    // 7) fc2 + bias + residual x2 (fp16) -> out fp32
    h_gemm<1024, false, false><<<dim3(2, 512), 256, HG_SMEM>>>(bigh, hf2, out, CC,
        nullptr, fc2_b, 0, x2h, 1.0f, nullptr);
}